// round 5
// baseline (speedup 1.0000x reference)
#include <cuda_runtime.h>
#include <cuda_bf16.h>
#include <math.h>
#include <stdint.h>

#define HH 256
#define WW 256
#define HWSZ 65536
#define BB 2
#define C64 64
#define C128 128
#define C256 256

#define SW128(off) ((off) ^ (((off) >> 3) & 0x70))

__device__ __forceinline__ uint32_t smem_u32(const void* p) {
    uint32_t a;
    asm("{ .reg .u64 t; cvta.to.shared.u64 t, %1; cvt.u32.u64 %0, t; }" : "=r"(a) : "l"(p));
    return a;
}
__device__ __forceinline__ void cpa16(uint32_t dst, const void* src, int sz) {
    asm volatile("cp.async.cg.shared.global [%0], [%1], 16, %2;"
                 :: "r"(dst), "l"(src), "r"(sz) : "memory");
}
__device__ __forceinline__ void cpa_commit() {
    asm volatile("cp.async.commit_group;" ::: "memory");
}
template<int N>
__device__ __forceinline__ void cpa_wait() {
    asm volatile("cp.async.wait_group %0;" :: "n"(N) : "memory");
}
__device__ __forceinline__ void ldm_x4(uint32_t& r0, uint32_t& r1, uint32_t& r2, uint32_t& r3,
                                       uint32_t addr) {
    asm volatile("ldmatrix.sync.aligned.m8n8.x4.shared.b16 {%0,%1,%2,%3}, [%4];"
                 : "=r"(r0), "=r"(r1), "=r"(r2), "=r"(r3) : "r"(addr));
}
__device__ __forceinline__ void mma16816(float* c, const uint32_t* a, uint32_t b0, uint32_t b1) {
    asm volatile("mma.sync.aligned.m16n8k16.row.col.f32.bf16.bf16.f32 "
                 "{%0,%1,%2,%3}, {%4,%5,%6,%7}, {%8,%9}, {%0,%1,%2,%3};"
                 : "+f"(c[0]), "+f"(c[1]), "+f"(c[2]), "+f"(c[3])
                 : "r"(a[0]), "r"(a[1]), "r"(a[2]), "r"(a[3]), "r"(b0), "r"(b1));
}

// ================= scratch (device globals) =================
__device__ float g_up   [BB * C64 * HWSZ];
__device__ float g_h1raw[BB * HWSZ * C64];
__device__ float g_b2   [BB * C64 * HWSZ];
__device__ float g_red[256];
__device__ float g_ab1[128];
__device__ float g_ab2[128];
__device__ __nv_bfloat16 g_x1_h[BB * 16384 * C64];
__device__ __nv_bfloat16 g_x1_l[BB * 16384 * C64];
__device__ __nv_bfloat16 g_cat_h[BB * HWSZ * C128];
__device__ __nv_bfloat16 g_cat_l[BB * HWSZ * C128];
__device__ __nv_bfloat16 g_xd_h [BB * HWSZ * C128];
__device__ __nv_bfloat16 g_xd_l [BB * HWSZ * C128];
__device__ __nv_bfloat16 g_h1_h [BB * HWSZ * C64];
__device__ __nv_bfloat16 g_h1_l [BB * HWSZ * C64];
__device__ __nv_bfloat16 g_wo_h[18 * C256 * 64];
__device__ __nv_bfloat16 g_wo_l[18 * C256 * 64];
__device__ __nv_bfloat16 g_w1_h[18 * C64 * 64];
__device__ __nv_bfloat16 g_w1_l[18 * C64 * 64];
__device__ __nv_bfloat16 g_w2_h[9 * C64 * 64];
__device__ __nv_bfloat16 g_w2_l[9 * C64 * 64];
__device__ __nv_bfloat16 g_wu_h[C256 * 64];
__device__ __nv_bfloat16 g_wu_l[C256 * 64];

// ================= weight prep =================
__global__ void wprep_k(const float* __restrict__ w, __nv_bfloat16* __restrict__ wh,
                        __nv_bfloat16* __restrict__ wl, int N, int CIN)
{
    int i = blockIdx.x * blockDim.x + threadIdx.x;
    if (i >= N * CIN * 9) return;
    int t  = i % 9;
    int ci = (i / 9) % CIN;
    int o  = i / (9 * CIN);
    int q = ci >> 6, cc = ci & 63;
    int kc = t * (CIN >> 6) + q;
    float v = w[i];
    __nv_bfloat16 h = __float2bfloat16(v);
    float lo = v - __bfloat162float(h);
    int dst = (kc * N + o) * 64 + cc;
    wh[dst] = h;
    wl[dst] = __float2bfloat16(lo);
}

__global__ void upwprep_k(const float* __restrict__ w, __nv_bfloat16* __restrict__ wh,
                          __nv_bfloat16* __restrict__ wl)
{
    int s = blockIdx.x * blockDim.x + threadIdx.x;
    if (s >= 64 * 256) return;
    int n = s & 255;
    int cc = s >> 8;
    float v = w[s];
    __nv_bfloat16 h = __float2bfloat16(v);
    float lo = v - __bfloat162float(h);
    wh[n * 64 + cc] = h;
    wl[n * 64 + cc] = __float2bfloat16(lo);
}

// ================= transpose-convert NCHW fp32 -> NHWC bf16 hi/lo =================
template<int C, int MODE, int HWN>
__global__ void __launch_bounds__(256)
tc_k(const float* __restrict__ in0, const float* __restrict__ in1,
     __nv_bfloat16* __restrict__ oh, __nv_bfloat16* __restrict__ ol)
{
    __shared__ float s[C][33];
    const int s0 = blockIdx.x * 32;
    const int b = blockIdx.y;
    const int tid = threadIdx.x;
    const int px = tid & 31;
#pragma unroll 4
    for (int c = tid >> 5; c < C; c += 8) {
        const float* src;
        if (MODE == 1)
            src = (c < 64) ? in0 + (b * 64 + c) * HWN : in1 + (b * 64 + (c - 64)) * HWN;
        else
            src = in0 + (b * C + c) * HWN;
        s[c][px] = src[s0 + px];
    }
    __syncthreads();
#pragma unroll 4
    for (int e = tid; e < 32 * C; e += 256) {
        int p = e / C, c = e % C;
        float v = s[c][p];
        __nv_bfloat16 h = __float2bfloat16(v);
        float lo = v - __bfloat162float(h);
        size_t idx = ((size_t)(b * HWN + s0 + p)) * C + c;
        oh[idx] = h;
        ol[idx] = __float2bfloat16(lo);
    }
}

// ================= upconv via mma: 1x1 GEMM =================
__global__ void __launch_bounds__(256, 2)
upmma_k(const __nv_bfloat16* __restrict__ ah_g, const __nv_bfloat16* __restrict__ al_g,
        const __nv_bfloat16* __restrict__ bh_g, const __nv_bfloat16* __restrict__ bl_g,
        const float* __restrict__ upb, float* __restrict__ up)
{
    extern __shared__ char dsm[];
    constexpr int A_H = 0, A_L = 16384, B_H = 32768, B_L = 40960;
    uint32_t raw = smem_u32(dsm);
    uint32_t base = (raw + 1023u) & ~1023u;
    char* smc = dsm + (base - raw);
    const int tid = threadIdx.x;
    const int wid = tid >> 5;
    const int lane = tid & 31;

    const int p0 = blockIdx.x * 128;
    const int b  = p0 >> 14;
    const int sb = p0 & 16383;
    const int y0 = sb >> 7;
    const int oc0 = blockIdx.y * 64;

#pragma unroll
    for (int it = 0; it < 4; it++) {
        int idx = it * 256 + tid;
        int m = idx >> 3, ch = idx & 7;
        size_t gi = ((size_t)(p0 + m)) * 64 + ch * 8;
        uint32_t sw = SW128(m * 128 + ch * 16);
        cpa16(base + A_H + sw, ah_g + gi, 16);
        cpa16(base + A_L + sw, al_g + gi, 16);
    }
#pragma unroll
    for (int it = 0; it < 2; it++) {
        int idx = it * 256 + tid;
        int o = idx >> 3, ch = idx & 7;
        size_t gi = ((size_t)(oc0 + o)) * 64 + ch * 8;
        uint32_t sw = SW128(o * 128 + ch * 16);
        cpa16(base + B_H + sw, bh_g + gi, 16);
        cpa16(base + B_L + sw, bl_g + gi, 16);
    }
    cpa_commit();
    cpa_wait<0>();
    __syncthreads();

    float acc[8][4];
#pragma unroll
    for (int g = 0; g < 8; g++)
#pragma unroll
        for (int j = 0; j < 4; j++) acc[g][j] = 0.f;

    const uint32_t Ah = base + A_H, Al = base + A_L;
    const uint32_t Bh = base + B_H, Bl = base + B_L;
    const int arow = wid * 16 + (lane & 15);
    const int nrow = lane & 15;
    const int chalf = (lane >> 4) * 16;
#pragma unroll
    for (int kk = 0; kk < 4; kk++) {
        const int cb = chalf + kk * 32;
        uint32_t ah[4], al[4];
        ldm_x4(ah[0], ah[1], ah[2], ah[3], Ah + SW128(arow * 128 + cb));
        ldm_x4(al[0], al[1], al[2], al[3], Al + SW128(arow * 128 + cb));
#pragma unroll
        for (int g = 0; g < 4; g++) {
            uint32_t off = SW128((g * 16 + nrow) * 128 + cb);
            uint32_t t0, t1, t2, t3, u0, u1, u2, u3;
            ldm_x4(t0, t1, t2, t3, Bh + off);
            ldm_x4(u0, u1, u2, u3, Bl + off);
            mma16816(acc[2 * g],     ah, t0, t2);
            mma16816(acc[2 * g + 1], ah, t1, t3);
            mma16816(acc[2 * g],     al, t0, t2);
            mma16816(acc[2 * g + 1], al, t1, t3);
            mma16816(acc[2 * g],     ah, u0, u2);
            mma16816(acc[2 * g + 1], ah, u1, u3);
        }
    }
    __syncthreads();

    float* sepi = (float*)smc;
    const int em = wid * 16 + (lane >> 2);
    const int en = (lane & 3) * 2;
#pragma unroll
    for (int g = 0; g < 8; g++) {
        int n0 = g * 8 + en;
        sepi[n0 * 132 + em]           = acc[g][0];
        sepi[(n0 + 1) * 132 + em]     = acc[g][1];
        sepi[n0 * 132 + em + 8]       = acc[g][2];
        sepi[(n0 + 1) * 132 + em + 8] = acc[g][3];
    }
    __syncthreads();
#pragma unroll 4
    for (int j = 0; j < 32; j++) {
        int lin = j * 256 + tid;
        int n = lin >> 7, m = lin & 127;
        int ng = oc0 + n;
        int o = ng >> 2, k = (ng >> 1) & 1, l = ng & 1;
        float v = sepi[n * 132 + m] + upb[o];
        up[((size_t)(b * 64 + o) << 16) + (2 * y0 + k) * 256 + 2 * m + l] = v;
    }
}

// ================= row-staged implicit-GEMM 3x3 conv (bf16x3) =================
// A band (3 x 130 pixel rows, hi/lo) staged ONCE per 64-ch group; 9 taps index it.
// Warp layout 4M x 2N; warp tile 32 x (NT/2).
// EPI 0: NCHW fp32 + bias + stats. EPI 1: NHWC fp32 + bias + stats.
// EPI 2: fused deformable gather -> xd NHWC hi/lo (coalesced via smem staging).
template<int NTOT, int CINQ, int NT, int EPI>
__global__ void __launch_bounds__(256, 1)
convmma_k(const __nv_bfloat16* __restrict__ ah_g, const __nv_bfloat16* __restrict__ al_g,
          const __nv_bfloat16* __restrict__ bh_g, const __nv_bfloat16* __restrict__ bl_g,
          const float* __restrict__ bias, float* __restrict__ out, float* __restrict__ red,
          const float* __restrict__ x2, const float* __restrict__ up,
          __nv_bfloat16* __restrict__ xdh, __nv_bfloat16* __restrict__ xdl)
{
    extern __shared__ char dsm[];
    constexpr int CCH  = CINQ * 64;
    constexpr int NW   = NT / 2;          // warp n-width
    constexpr int NG   = NW / 16;         // 16-col groups per warp
    constexpr int A_PL = 50176;           // bytes per A plane (392 rows x 128B)
    constexpr int B_OFF = 100352;
    constexpr int B_BUF = NT * 256;       // bytes per B buffer (hi+lo)

    uint32_t raw = smem_u32(dsm);
    uint32_t base = (raw + 1023u) & ~1023u;
    char* smc = dsm + (base - raw);
    const int tid = threadIdx.x;
    const int wid = tid >> 5;
    const int lane = tid & 31;
    const int mw = wid & 3;
    const int nw = wid >> 2;

    const int p0 = blockIdx.x * 128;
    const int b  = p0 >> 16;
    const int sb = p0 & 65535;
    const int y0 = sb >> 8;
    const int x0 = sb & 255;
    const int oc0 = blockIdx.y * NT;

    auto stageA = [&](int q) {
#pragma unroll
        for (int pl = 0; pl < 2; pl++) {
            const __nv_bfloat16* sp = pl ? al_g : ah_g;
            uint32_t abase = base + pl * A_PL;
            for (int idx = tid; idx < 3120; idx += 256) {
                int r = idx >> 3, ch = idx & 7;
                int ry = y0 + (r / 130) - 1;
                int rx = x0 + (r % 130) - 1;
                bool inb = ((unsigned)ry < 256u) && ((unsigned)rx < 256u);
                size_t gi = (((size_t)b << 16) + (ry << 8) + rx) * CCH + q * 64 + ch * 8;
                if (!inb) gi = 0;
                cpa16(abase + SW128(r * 128 + ch * 16), sp + gi, inb ? 16 : 0);
            }
        }
    };
    auto stageB = [&](int chunk, int buf) {
        int q = chunk / 9, t = chunk - q * 9;
        uint32_t bbase = base + B_OFF + buf * B_BUF;
        for (int idx = tid; idx < NT * 8; idx += 256) {
            int o = idx >> 3, ch = idx & 7;
            size_t gi = ((size_t)(t * CINQ + q) * NTOT + oc0 + o) * 64 + ch * 8;
            uint32_t sw = SW128(o * 128 + ch * 16);
            cpa16(bbase + sw, bh_g + gi, 16);
            cpa16(bbase + NT * 128 + sw, bl_g + gi, 16);
        }
    };

    float acc[2][NW / 8][4];
#pragma unroll
    for (int ms = 0; ms < 2; ms++)
#pragma unroll
        for (int g = 0; g < NW / 8; g++)
#pragma unroll
            for (int j = 0; j < 4; j++) acc[ms][g][j] = 0.f;

    stageA(0);
    stageB(0, 0);
    cpa_commit();

    const int chalf = (lane >> 4) * 16;
    const int nrow = lane & 15;
    const int alane = lane & 15;

#pragma unroll 1
    for (int q = 0; q < CINQ; q++) {
#pragma unroll 1
        for (int t = 0; t < 9; t++) {
            const int chunk = q * 9 + t;
            const bool hasNext = (chunk + 1) < CINQ * 9;
            if (hasNext) {
                stageB(chunk + 1, (chunk + 1) & 1);
                cpa_commit();
                cpa_wait<1>();
            } else {
                cpa_wait<0>();
            }
            __syncthreads();

            const int ky = t / 3 - 1;
            const int kx = t % 3 - 1;
            const uint32_t Ah = base;
            const uint32_t Al = base + A_PL;
            const uint32_t Bb = base + B_OFF + (chunk & 1) * B_BUF;
            const uint32_t Bh = Bb, Bl = Bb + NT * 128;
            const int rbase = (ky + 1) * 130 + mw * 32 + alane + kx + 1;

#pragma unroll
            for (int kk = 0; kk < 4; kk++) {
                const int cb = chalf + kk * 32;
                uint32_t ah[2][4], al[2][4];
#pragma unroll
                for (int ms = 0; ms < 2; ms++) {
                    int r = rbase + ms * 16;
                    ldm_x4(ah[ms][0], ah[ms][1], ah[ms][2], ah[ms][3],
                           Ah + SW128(r * 128 + cb));
                    ldm_x4(al[ms][0], al[ms][1], al[ms][2], al[ms][3],
                           Al + SW128(r * 128 + cb));
                }
#pragma unroll
                for (int g = 0; g < NG; g++) {
                    uint32_t off = SW128((nw * NW + g * 16 + nrow) * 128 + cb);
                    uint32_t t0, t1, t2, t3, u0, u1, u2, u3;
                    ldm_x4(t0, t1, t2, t3, Bh + off);
                    ldm_x4(u0, u1, u2, u3, Bl + off);
#pragma unroll
                    for (int ms = 0; ms < 2; ms++) {
                        mma16816(acc[ms][2 * g],     ah[ms], t0, t2);
                        mma16816(acc[ms][2 * g + 1], ah[ms], t1, t3);
                        mma16816(acc[ms][2 * g],     al[ms], t0, t2);
                        mma16816(acc[ms][2 * g + 1], al[ms], t1, t3);
                        mma16816(acc[ms][2 * g],     ah[ms], u0, u2);
                        mma16816(acc[ms][2 * g + 1], ah[ms], u1, u3);
                    }
                }
            }
            __syncthreads();
        }
        if (q + 1 < CINQ) {
            stageA(q + 1);
            cpa_commit();
        }
    }

    // ---- stage [n][m] in smem (reuse A region) ----
    float* sepi = (float*)smc;
    const int em = mw * 32 + (lane >> 2);
    const int ecol = (lane & 3) * 2;
#pragma unroll
    for (int ms = 0; ms < 2; ms++) {
        int m = em + ms * 16;
#pragma unroll
        for (int g = 0; g < NG; g++) {
            int nb = nw * NW + g * 16 + ecol;
            sepi[nb * 132 + m]           = acc[ms][2 * g][0];
            sepi[(nb + 1) * 132 + m]     = acc[ms][2 * g][1];
            sepi[nb * 132 + m + 8]       = acc[ms][2 * g][2];
            sepi[(nb + 1) * 132 + m + 8] = acc[ms][2 * g][3];
            int nb2 = nb + 8;
            sepi[nb2 * 132 + m]           = acc[ms][2 * g + 1][0];
            sepi[(nb2 + 1) * 132 + m]     = acc[ms][2 * g + 1][1];
            sepi[nb2 * 132 + m + 8]       = acc[ms][2 * g + 1][2];
            sepi[(nb2 + 1) * 132 + m + 8] = acc[ms][2 * g + 1][3];
        }
    }
    __syncthreads();

    if (EPI == 0) {
#pragma unroll
        for (int j = 0; j < NT / 8; j++) {
            int lin = j * 256 + tid;
            int n = lin >> 5;
            int seg = lin & 31;
            float4 v = *(float4*)(sepi + n * 132 + seg * 4);
            float bz = bias[oc0 + n];
            v.x += bz; v.y += bz; v.z += bz; v.w += bz;
            *(float4*)(out + (((size_t)(b * NTOT + oc0 + n)) << 16) + sb + seg * 4) = v;
        }
    } else if (EPI == 1) {
#pragma unroll
        for (int j = 0; j < NT / 8; j++) {
            int lin = j * 256 + tid;
            int m = lin >> 4;
            int cq = lin & 15;
            float4 v;
            v.x = sepi[(cq * 4 + 0) * 132 + m] + bias[cq * 4 + 0];
            v.y = sepi[(cq * 4 + 1) * 132 + m] + bias[cq * 4 + 1];
            v.z = sepi[(cq * 4 + 2) * 132 + m] + bias[cq * 4 + 2];
            v.w = sepi[(cq * 4 + 3) * 132 + m] + bias[cq * 4 + 3];
            *(float4*)(out + ((size_t)(b * 65536 + sb + m)) * 64 + cq * 4) = v;
        }
    } else {
        // fused deformable gather: NT=128 slice -> 128 pixels x 64 channels
        float* sval = (float*)(smc + B_OFF);   // [128][68]
#pragma unroll 1
        for (int it = 0; it < 16; it++) {
            int idx = it * 256 + tid;          // 0..4095
            int ql = idx >> 5;                 // 0..127
            int eh = idx & 31;
#pragma unroll
            for (int ee = 0; ee < 2; ee++) {
                int e = eh * 2 + ee;           // 0..63
                int m = 2 * e;
                int q = oc0 + ql;
                int c = q >> 1;
                float oy = sepi[ql * 132 + m];
                float ox = sepi[ql * 132 + m + 1];
                int rem = ((q & 1) << 16) + sb + m;
                int h = rem >> 9;
                int w = (rem >> 1) & 255;
                const float* src = (c < 64) ? x2 + ((size_t)(b * 64 + c) << 16)
                                            : up + ((size_t)(b * 64 + c - 64) << 16);
                float cy = fminf(fmaxf(oy + (float)h, 0.f), 255.f);
                float cx = fminf(fmaxf(ox + (float)w, 0.f), 255.f);
                float y0f = floorf(cy), x0f = floorf(cx);
                int iy0 = (int)y0f;
                int ix0 = (int)x0f;
                int iy1 = (int)ceilf(cy);
                int ix1 = (int)ceilf(cx);
                float v00 = src[iy0 * 256 + ix0];
                float v10 = src[iy1 * 256 + ix0];
                float v01 = src[iy0 * 256 + ix1];
                float v11 = src[iy1 * 256 + ix1];
                float wy = cy - y0f, wx = cx - x0f;
                float vt = v00 + (v10 - v00) * wy;
                float vb = v01 + (v11 - v01) * wy;
                int parity = ql & 1;
                int pp = (parity << 6) + e;
                sval[pp * 68 + (ql >> 1)] = vt + (vb - vt) * wx;
            }
        }
        __syncthreads();
        // coalesced NHWC hi/lo writes: 2 threads per pixel, 32 ch each
        {
            int pp = tid >> 1, half = tid & 1;
            int parity = pp >> 6, e = pp & 63;
            int pixel = (parity << 15) + (sb >> 1) + e;
            const float* vs = sval + pp * 68 + half * 32;
            unsigned short hs[32], ls[32];
#pragma unroll
            for (int j = 0; j < 32; j++) {
                float v = vs[j];
                __nv_bfloat16 hb = __float2bfloat16(v);
                float lo = v - __bfloat162float(hb);
                __nv_bfloat16 lb = __float2bfloat16(lo);
                hs[j] = *(unsigned short*)&hb;
                ls[j] = *(unsigned short*)&lb;
            }
            size_t og = ((size_t)(b * 65536 + pixel)) * 128 + (oc0 >> 1) + half * 32;
            uint4* dh = (uint4*)((unsigned short*)xdh + og);
            uint4* dl = (uint4*)((unsigned short*)xdl + og);
#pragma unroll
            for (int j = 0; j < 4; j++) {
                dh[j] = ((uint4*)hs)[j];
                dl[j] = ((uint4*)ls)[j];
            }
        }
    }

    if (EPI == 0 || EPI == 1) {
        float* sred = sepi + NT * 132;
        int n = tid >> 2, part = tid & 3;
        float bz = bias[oc0 + n];
        float s1 = 0.f, s2 = 0.f;
        const float* rowp = sepi + n * 132 + part * 32;
#pragma unroll
        for (int j = 0; j < 32; j++) {
            float v = rowp[j] + bz;
            s1 += v;
            s2 = fmaf(v, v, s2);
        }
        sred[(0 * 64 + n) * 4 + part] = s1;
        sred[(1 * 64 + n) * 4 + part] = s2;
        __syncthreads();
        if (tid < 128) {
            int which = tid >> 6, n2 = tid & 63;
            const float* pr = sred + (which * 64 + n2) * 4;
            atomicAdd(red + which * 64 + oc0 + n2, pr[0] + pr[1] + pr[2] + pr[3]);
        }
    }
}

// ================= small kernels =================
__global__ void zero_red_k() { g_red[threadIdx.x] = 0.f; }

__global__ void bnfin_k(const float* __restrict__ red,
                        const float* __restrict__ gamma, const float* __restrict__ beta,
                        float* __restrict__ ab)
{
    int c = threadIdx.x;
    const float invn = 1.f / 131072.f;
    float m = red[c] * invn;
    float var = fmaf(-m, m, red[64 + c] * invn);
    float a = gamma[c] * rsqrtf(var + 1e-5f);
    ab[c] = a;
    ab[64 + c] = fmaf(-m, a, beta[c]);
}

__global__ void __launch_bounds__(256)
afsplit_k(const float* __restrict__ in, const float* __restrict__ ab,
          __nv_bfloat16* __restrict__ oh, __nv_bfloat16* __restrict__ ol)
{
    int i4 = blockIdx.x * 256 + threadIdx.x;
    int c0 = (i4 & 15) * 4;
    float4 v = *(const float4*)(in + (size_t)i4 * 4);
    float vv[4] = {v.x, v.y, v.z, v.w};
    unsigned short hs[4], ls[4];
#pragma unroll
    for (int j = 0; j < 4; j++) {
        int c = c0 + j;
        float y = fmaxf(fmaf(vv[j], __ldg(ab + c), __ldg(ab + 64 + c)), 0.f);
        __nv_bfloat16 hb = __float2bfloat16(y);
        float lo = y - __bfloat162float(hb);
        __nv_bfloat16 lb = __float2bfloat16(lo);
        hs[j] = *(unsigned short*)&hb;
        ls[j] = *(unsigned short*)&lb;
    }
    *(uint2*)((unsigned short*)oh + (size_t)i4 * 4) = *(uint2*)hs;
    *(uint2*)((unsigned short*)ol + (size_t)i4 * 4) = *(uint2*)ls;
}

__global__ void __launch_bounds__(256)
bnrelu_out_k(const float* __restrict__ buf, const float* __restrict__ ab,
             float* __restrict__ out)
{
    int i4 = blockIdx.x * 256 + threadIdx.x;
    int c = (i4 >> 14) & 63;
    float a = __ldg(ab + c), bz = __ldg(ab + 64 + c);
    float4 v = *(const float4*)(buf + (size_t)i4 * 4);
    v.x = fmaxf(fmaf(v.x, a, bz), 0.f);
    v.y = fmaxf(fmaf(v.y, a, bz), 0.f);
    v.z = fmaxf(fmaf(v.z, a, bz), 0.f);
    v.w = fmaxf(fmaf(v.w, a, bz), 0.f);
    *(float4*)(out + (size_t)i4 * 4) = v;
}

// ================= launch =================
extern "C" void kernel_launch(void* const* d_in, const int* in_sizes, int n_in,
                              void* d_out, int out_size)
{
    const float* x1   = (const float*)d_in[0];
    const float* x2   = (const float*)d_in[1];
    const float* up_w = (const float*)d_in[2];
    const float* up_b = (const float*)d_in[3];
    const float* offw = (const float*)d_in[4];
    const float* c1w  = (const float*)d_in[5];
    const float* c1b  = (const float*)d_in[6];
    const float* g1   = (const float*)d_in[7];
    const float* b1   = (const float*)d_in[8];
    const float* c2w  = (const float*)d_in[9];
    const float* c2b  = (const float*)d_in[10];
    const float* g2   = (const float*)d_in[11];
    const float* b2   = (const float*)d_in[12];
    float* outp = (float*)d_out;

    float *p_up, *p_h1raw, *p_b2, *p_red, *p_ab1, *p_ab2;
    cudaGetSymbolAddress((void**)&p_up,    g_up);
    cudaGetSymbolAddress((void**)&p_h1raw, g_h1raw);
    cudaGetSymbolAddress((void**)&p_b2,    g_b2);
    cudaGetSymbolAddress((void**)&p_red,   g_red);
    cudaGetSymbolAddress((void**)&p_ab1,   g_ab1);
    cudaGetSymbolAddress((void**)&p_ab2,   g_ab2);
    __nv_bfloat16 *p_x1_h, *p_x1_l, *p_cat_h, *p_cat_l, *p_xd_h, *p_xd_l, *p_h1_h, *p_h1_l;
    __nv_bfloat16 *p_wo_h, *p_wo_l, *p_w1_h, *p_w1_l, *p_w2_h, *p_w2_l, *p_wu_h, *p_wu_l;
    cudaGetSymbolAddress((void**)&p_x1_h, g_x1_h);
    cudaGetSymbolAddress((void**)&p_x1_l, g_x1_l);
    cudaGetSymbolAddress((void**)&p_cat_h, g_cat_h);
    cudaGetSymbolAddress((void**)&p_cat_l, g_cat_l);
    cudaGetSymbolAddress((void**)&p_xd_h, g_xd_h);
    cudaGetSymbolAddress((void**)&p_xd_l, g_xd_l);
    cudaGetSymbolAddress((void**)&p_h1_h, g_h1_h);
    cudaGetSymbolAddress((void**)&p_h1_l, g_h1_l);
    cudaGetSymbolAddress((void**)&p_wo_h, g_wo_h);
    cudaGetSymbolAddress((void**)&p_wo_l, g_wo_l);
    cudaGetSymbolAddress((void**)&p_w1_h, g_w1_h);
    cudaGetSymbolAddress((void**)&p_w1_l, g_w1_l);
    cudaGetSymbolAddress((void**)&p_w2_h, g_w2_h);
    cudaGetSymbolAddress((void**)&p_w2_l, g_w2_l);
    cudaGetSymbolAddress((void**)&p_wu_h, g_wu_h);
    cudaGetSymbolAddress((void**)&p_wu_l, g_wu_l);

    const int smem_off = 1024 + 100352 + 65536;   // 166912
    const int smem_c   = 1024 + 100352 + 32768;   // 134144
    const int smem_up  = 49152 + 1024;
    cudaFuncSetAttribute(convmma_k<256, 2, 128, 2>, cudaFuncAttributeMaxDynamicSharedMemorySize, smem_off);
    cudaFuncSetAttribute(convmma_k<64, 2, 64, 1>,   cudaFuncAttributeMaxDynamicSharedMemorySize, smem_c);
    cudaFuncSetAttribute(convmma_k<64, 1, 64, 0>,   cudaFuncAttributeMaxDynamicSharedMemorySize, smem_c);
    cudaFuncSetAttribute(upmma_k, cudaFuncAttributeMaxDynamicSharedMemorySize, smem_up);

    // 0) zero stats + weight prep
    zero_red_k<<<1, 256>>>();
    wprep_k<<<(256 * 128 * 9 + 255) / 256, 256>>>(offw, p_wo_h, p_wo_l, 256, 128);
    wprep_k<<<(64 * 128 * 9 + 255) / 256, 256>>>(c1w, p_w1_h, p_w1_l, 64, 128);
    wprep_k<<<(64 * 64 * 9 + 255) / 256, 256>>>(c2w, p_w2_h, p_w2_l, 64, 64);
    upwprep_k<<<64, 256>>>(up_w, p_wu_h, p_wu_l);

    // 1) x1 -> NHWC hi/lo, upconv via mma
    tc_k<64, 0, 16384><<<dim3(512, 2), 256>>>(x1, nullptr, p_x1_h, p_x1_l);
    upmma_k<<<dim3(256, 4), 256, smem_up>>>(p_x1_h, p_x1_l, p_wu_h, p_wu_l, up_b, p_up);

    // 2) concat -> NHWC bf16 hi/lo
    tc_k<128, 1, 65536><<<dim3(2048, 2), 256>>>(x2, p_up, p_cat_h, p_cat_l);

    // 3) offset conv + fused deformable gather -> xd NHWC hi/lo
    convmma_k<256, 2, 128, 2><<<dim3(1024, 2), 256, smem_off>>>(
        p_cat_h, p_cat_l, p_wo_h, p_wo_l, nullptr, nullptr, nullptr,
        x2, p_up, p_xd_h, p_xd_l);

    // 4) conv1 -> NHWC fp32 + fused BN1 stats
    convmma_k<64, 2, 64, 1><<<dim3(1024, 1), 256, smem_c>>>(
        p_xd_h, p_xd_l, p_w1_h, p_w1_l, c1b, p_h1raw, p_red,
        nullptr, nullptr, nullptr, nullptr);
    bnfin_k<<<1, 64>>>(p_red, g1, b1, p_ab1);

    // 5) BN1 affine + relu + split
    afsplit_k<<<8192, 256>>>(p_h1raw, p_ab1, p_h1_h, p_h1_l);

    // 6) conv2 -> NCHW fp32 + fused BN2 stats
    convmma_k<64, 1, 64, 0><<<dim3(1024, 1), 256, smem_c>>>(
        p_h1_h, p_h1_l, p_w2_h, p_w2_l, c2b, p_b2, p_red + 128,
        nullptr, nullptr, nullptr, nullptr);
    bnfin_k<<<1, 64>>>(p_red + 128, g2, b2, p_ab2);

    // 7) final BN+ReLU
    bnrelu_out_k<<<8192, 256>>>(p_b2, p_ab2, outp);
}

// round 6
// speedup vs baseline: 1.0930x; 1.0930x over previous
#include <cuda_runtime.h>
#include <cuda_bf16.h>
#include <math.h>
#include <stdint.h>

#define HH 256
#define WW 256
#define HWSZ 65536
#define BB 2
#define C64 64
#define C128 128
#define C256 256

#define SW128(off) ((off) ^ (((off) >> 3) & 0x70))

__device__ __forceinline__ uint32_t smem_u32(const void* p) {
    uint32_t a;
    asm("{ .reg .u64 t; cvta.to.shared.u64 t, %1; cvt.u32.u64 %0, t; }" : "=r"(a) : "l"(p));
    return a;
}
__device__ __forceinline__ void cpa16(uint32_t dst, const void* src, int sz) {
    asm volatile("cp.async.cg.shared.global [%0], [%1], 16, %2;"
                 :: "r"(dst), "l"(src), "r"(sz) : "memory");
}
__device__ __forceinline__ void cpa_commit() {
    asm volatile("cp.async.commit_group;" ::: "memory");
}
template<int N>
__device__ __forceinline__ void cpa_wait() {
    asm volatile("cp.async.wait_group %0;" :: "n"(N) : "memory");
}
__device__ __forceinline__ void ldm_x4(uint32_t& r0, uint32_t& r1, uint32_t& r2, uint32_t& r3,
                                       uint32_t addr) {
    asm volatile("ldmatrix.sync.aligned.m8n8.x4.shared.b16 {%0,%1,%2,%3}, [%4];"
                 : "=r"(r0), "=r"(r1), "=r"(r2), "=r"(r3) : "r"(addr));
}
__device__ __forceinline__ void mma16816(float* c, const uint32_t* a, uint32_t b0, uint32_t b1) {
    asm volatile("mma.sync.aligned.m16n8k16.row.col.f32.bf16.bf16.f32 "
                 "{%0,%1,%2,%3}, {%4,%5,%6,%7}, {%8,%9}, {%0,%1,%2,%3};"
                 : "+f"(c[0]), "+f"(c[1]), "+f"(c[2]), "+f"(c[3])
                 : "r"(a[0]), "r"(a[1]), "r"(a[2]), "r"(a[3]), "r"(b0), "r"(b1));
}

// ================= scratch (device globals) =================
__device__ float g_up   [BB * C64 * HWSZ];
__device__ float g_off  [BB * C256 * HWSZ];
__device__ float g_h1raw[BB * HWSZ * C64];
__device__ float g_b2   [BB * C64 * HWSZ];
__device__ float g_red[256];
__device__ float g_ab1[128];
__device__ float g_ab2[128];
__device__ __nv_bfloat16 g_x1_h[BB * 16384 * C64];
__device__ __nv_bfloat16 g_x1_l[BB * 16384 * C64];
__device__ __nv_bfloat16 g_cat_h[BB * HWSZ * C128];
__device__ __nv_bfloat16 g_cat_l[BB * HWSZ * C128];
__device__ __nv_bfloat16 g_xd_h [BB * HWSZ * C128];
__device__ __nv_bfloat16 g_xd_l [BB * HWSZ * C128];
__device__ __nv_bfloat16 g_h1_h [BB * HWSZ * C64];
__device__ __nv_bfloat16 g_h1_l [BB * HWSZ * C64];
__device__ __nv_bfloat16 g_wo_h[18 * C256 * 64];
__device__ __nv_bfloat16 g_wo_l[18 * C256 * 64];
__device__ __nv_bfloat16 g_w1_h[18 * C64 * 64];
__device__ __nv_bfloat16 g_w1_l[18 * C64 * 64];
__device__ __nv_bfloat16 g_w2_h[9 * C64 * 64];
__device__ __nv_bfloat16 g_w2_l[9 * C64 * 64];
__device__ __nv_bfloat16 g_wu_h[C256 * 64];
__device__ __nv_bfloat16 g_wu_l[C256 * 64];

// ================= weight prep =================
__global__ void wprep_k(const float* __restrict__ w, __nv_bfloat16* __restrict__ wh,
                        __nv_bfloat16* __restrict__ wl, int N, int CIN)
{
    int i = blockIdx.x * blockDim.x + threadIdx.x;
    if (i >= N * CIN * 9) return;
    int t  = i % 9;
    int ci = (i / 9) % CIN;
    int o  = i / (9 * CIN);
    int q = ci >> 6, cc = ci & 63;
    int kc = t * (CIN >> 6) + q;
    float v = w[i];
    __nv_bfloat16 h = __float2bfloat16(v);
    float lo = v - __bfloat162float(h);
    int dst = (kc * N + o) * 64 + cc;
    wh[dst] = h;
    wl[dst] = __float2bfloat16(lo);
}

__global__ void upwprep_k(const float* __restrict__ w, __nv_bfloat16* __restrict__ wh,
                          __nv_bfloat16* __restrict__ wl)
{
    int s = blockIdx.x * blockDim.x + threadIdx.x;
    if (s >= 64 * 256) return;
    int n = s & 255;
    int cc = s >> 8;
    float v = w[s];
    __nv_bfloat16 h = __float2bfloat16(v);
    float lo = v - __bfloat162float(h);
    wh[n * 64 + cc] = h;
    wl[n * 64 + cc] = __float2bfloat16(lo);
}

// ================= transpose-convert NCHW fp32 -> NHWC bf16 hi/lo =================
template<int C, int MODE, int HWN>
__global__ void __launch_bounds__(256)
tc_k(const float* __restrict__ in0, const float* __restrict__ in1,
     __nv_bfloat16* __restrict__ oh, __nv_bfloat16* __restrict__ ol)
{
    __shared__ float s[C][33];
    const int s0 = blockIdx.x * 32;
    const int b = blockIdx.y;
    const int tid = threadIdx.x;
    const int px = tid & 31;
#pragma unroll 4
    for (int c = tid >> 5; c < C; c += 8) {
        const float* src;
        if (MODE == 1)
            src = (c < 64) ? in0 + (b * 64 + c) * HWN : in1 + (b * 64 + (c - 64)) * HWN;
        else
            src = in0 + (b * C + c) * HWN;
        s[c][px] = src[s0 + px];
    }
    __syncthreads();
#pragma unroll 4
    for (int e = tid; e < 32 * C; e += 256) {
        int p = e / C, c = e % C;
        float v = s[c][p];
        __nv_bfloat16 h = __float2bfloat16(v);
        float lo = v - __bfloat162float(h);
        size_t idx = ((size_t)(b * HWN + s0 + p)) * C + c;
        oh[idx] = h;
        ol[idx] = __float2bfloat16(lo);
    }
}

// ================= upconv via mma: 1x1 GEMM =================
__global__ void __launch_bounds__(256, 2)
upmma_k(const __nv_bfloat16* __restrict__ ah_g, const __nv_bfloat16* __restrict__ al_g,
        const __nv_bfloat16* __restrict__ bh_g, const __nv_bfloat16* __restrict__ bl_g,
        const float* __restrict__ upb, float* __restrict__ up)
{
    extern __shared__ char dsm[];
    constexpr int A_H = 0, A_L = 16384, B_H = 32768, B_L = 40960;
    uint32_t raw = smem_u32(dsm);
    uint32_t base = (raw + 1023u) & ~1023u;
    char* smc = dsm + (base - raw);
    const int tid = threadIdx.x;
    const int wid = tid >> 5;
    const int lane = tid & 31;

    const int p0 = blockIdx.x * 128;
    const int b  = p0 >> 14;
    const int sb = p0 & 16383;
    const int y0 = sb >> 7;
    const int oc0 = blockIdx.y * 64;

#pragma unroll
    for (int it = 0; it < 4; it++) {
        int idx = it * 256 + tid;
        int m = idx >> 3, ch = idx & 7;
        size_t gi = ((size_t)(p0 + m)) * 64 + ch * 8;
        uint32_t sw = SW128(m * 128 + ch * 16);
        cpa16(base + A_H + sw, ah_g + gi, 16);
        cpa16(base + A_L + sw, al_g + gi, 16);
    }
#pragma unroll
    for (int it = 0; it < 2; it++) {
        int idx = it * 256 + tid;
        int o = idx >> 3, ch = idx & 7;
        size_t gi = ((size_t)(oc0 + o)) * 64 + ch * 8;
        uint32_t sw = SW128(o * 128 + ch * 16);
        cpa16(base + B_H + sw, bh_g + gi, 16);
        cpa16(base + B_L + sw, bl_g + gi, 16);
    }
    cpa_commit();
    cpa_wait<0>();
    __syncthreads();

    float acc[8][4];
#pragma unroll
    for (int g = 0; g < 8; g++)
#pragma unroll
        for (int j = 0; j < 4; j++) acc[g][j] = 0.f;

    const uint32_t Ah = base + A_H, Al = base + A_L;
    const uint32_t Bh = base + B_H, Bl = base + B_L;
    const int arow = wid * 16 + (lane & 15);
    const int nrow = lane & 15;
    const int chalf = (lane >> 4) * 16;
#pragma unroll
    for (int kk = 0; kk < 4; kk++) {
        const int cb = chalf + kk * 32;
        uint32_t ah[4], al[4];
        ldm_x4(ah[0], ah[1], ah[2], ah[3], Ah + SW128(arow * 128 + cb));
        ldm_x4(al[0], al[1], al[2], al[3], Al + SW128(arow * 128 + cb));
#pragma unroll
        for (int g = 0; g < 4; g++) {
            uint32_t off = SW128((g * 16 + nrow) * 128 + cb);
            uint32_t t0, t1, t2, t3, u0, u1, u2, u3;
            ldm_x4(t0, t1, t2, t3, Bh + off);
            ldm_x4(u0, u1, u2, u3, Bl + off);
            mma16816(acc[2 * g],     ah, t0, t2);
            mma16816(acc[2 * g + 1], ah, t1, t3);
            mma16816(acc[2 * g],     al, t0, t2);
            mma16816(acc[2 * g + 1], al, t1, t3);
            mma16816(acc[2 * g],     ah, u0, u2);
            mma16816(acc[2 * g + 1], ah, u1, u3);
        }
    }
    __syncthreads();

    float* sepi = (float*)smc;
    const int em = wid * 16 + (lane >> 2);
    const int en = (lane & 3) * 2;
#pragma unroll
    for (int g = 0; g < 8; g++) {
        int n0 = g * 8 + en;
        sepi[n0 * 132 + em]           = acc[g][0];
        sepi[(n0 + 1) * 132 + em]     = acc[g][1];
        sepi[n0 * 132 + em + 8]       = acc[g][2];
        sepi[(n0 + 1) * 132 + em + 8] = acc[g][3];
    }
    __syncthreads();
#pragma unroll 4
    for (int j = 0; j < 32; j++) {
        int lin = j * 256 + tid;
        int n = lin >> 7, m = lin & 127;
        int ng = oc0 + n;
        int o = ng >> 2, k = (ng >> 1) & 1, l = ng & 1;
        float v = sepi[n * 132 + m] + upb[o];
        up[((size_t)(b * 64 + o) << 16) + (2 * y0 + k) * 256 + 2 * m + l] = v;
    }
}

// ================= implicit-GEMM 3x3 conv (bf16x3), M=256 (one image row) =================
// 512 threads / 16 warps (8M x 2N). Per-tap double-buffered staging (R3-style loop).
// EPI 0: NCHW fp32 (+bias if set, +stats if red set). EPI 1: NHWC fp32 + bias + stats.
template<int NTOT, int CINQ, int NT, int EPI>
__global__ void __launch_bounds__(512, 1)
convmma_k(const __nv_bfloat16* __restrict__ ah_g, const __nv_bfloat16* __restrict__ al_g,
          const __nv_bfloat16* __restrict__ bh_g, const __nv_bfloat16* __restrict__ bl_g,
          const float* __restrict__ bias, float* __restrict__ out, float* __restrict__ red)
{
    extern __shared__ char dsm[];
    constexpr int CCH = CINQ * 64;
    constexpr int NC  = CINQ * 9;
    constexpr int NW  = NT / 2;
    constexpr int NG  = NW / 16;
    constexpr int A_L   = 32768;              // A: 256 rows x 128B per plane
    constexpr int B_OFF = 65536;
    constexpr int STAGE = 65536 + NT * 256;   // A(64K) + B(NT*128 hi + NT*128 lo)

    uint32_t raw = smem_u32(dsm);
    uint32_t base = (raw + 1023u) & ~1023u;
    char* smc = dsm + (base - raw);
    const int tid = threadIdx.x;
    const int wid = tid >> 5;
    const int lane = tid & 31;
    const int mw = wid & 7;
    const int nw = wid >> 3;

    const int b  = blockIdx.x >> 8;
    const int y0 = blockIdx.x & 255;
    const int sb = y0 << 8;
    const int oc0 = blockIdx.y * NT;

    auto stage = [&](int chunk, int buf) {
        const int t = chunk / CINQ;
        const int q = chunk - t * CINQ;
        const int ky = t / 3 - 1;
        const int kx = t % 3 - 1;
        const uint32_t sbase = base + buf * STAGE;
        const int yy = y0 + ky;
        const bool yin = (unsigned)yy < 256u;
        // A: 256 rows x 8 ch-chunks, hi+lo
#pragma unroll
        for (int it = 0; it < 4; it++) {
            int idx = it * 512 + tid;          // 0..2047
            int m = idx >> 3, ch = idx & 7;
            int xx = m + kx;
            bool inb = yin && ((unsigned)xx < 256u);
            size_t gi = (((size_t)b << 16) + (yy << 8) + xx) * CCH + q * 64 + ch * 8;
            if (!inb) gi = 0;
            uint32_t sw = SW128(m * 128 + ch * 16);
            int sz = inb ? 16 : 0;
            cpa16(sbase + sw, ah_g + gi, sz);
            cpa16(sbase + A_L + sw, al_g + gi, sz);
        }
        // B: NT rows x 8 ch-chunks, hi+lo
        for (int idx = tid; idx < NT * 8; idx += 512) {
            int o = idx >> 3, ch = idx & 7;
            size_t gi = ((size_t)chunk * NTOT + oc0 + o) * 64 + ch * 8;
            uint32_t sw = SW128(o * 128 + ch * 16);
            cpa16(sbase + B_OFF + sw, bh_g + gi, 16);
            cpa16(sbase + B_OFF + NT * 128 + sw, bl_g + gi, 16);
        }
        cpa_commit();
    };

    float acc[2][NW / 8][4];
#pragma unroll
    for (int ms = 0; ms < 2; ms++)
#pragma unroll
        for (int g = 0; g < NW / 8; g++)
#pragma unroll
            for (int j = 0; j < 4; j++) acc[ms][g][j] = 0.f;

    stage(0, 0);

    const int chalf = (lane >> 4) * 16;
    const int nrow = lane & 15;
    const int arowb = mw * 32 + (lane & 15);

#pragma unroll 1
    for (int chunk = 0; chunk < NC; chunk++) {
        if (chunk + 1 < NC) {
            stage(chunk + 1, (chunk + 1) & 1);
            cpa_wait<1>();
        } else {
            cpa_wait<0>();
        }
        __syncthreads();

        const uint32_t sbase = base + (chunk & 1) * STAGE;
        const uint32_t Ah = sbase, Al = sbase + A_L;
        const uint32_t Bh = sbase + B_OFF, Bl = sbase + B_OFF + NT * 128;

#pragma unroll
        for (int kk = 0; kk < 4; kk++) {
            const int cb = chalf + kk * 32;
            uint32_t ah[2][4], al[2][4];
#pragma unroll
            for (int ms = 0; ms < 2; ms++) {
                int r = arowb + ms * 16;
                ldm_x4(ah[ms][0], ah[ms][1], ah[ms][2], ah[ms][3], Ah + SW128(r * 128 + cb));
                ldm_x4(al[ms][0], al[ms][1], al[ms][2], al[ms][3], Al + SW128(r * 128 + cb));
            }
#pragma unroll
            for (int g = 0; g < NG; g++) {
                uint32_t off = SW128((nw * NW + g * 16 + nrow) * 128 + cb);
                uint32_t t0, t1, t2, t3, u0, u1, u2, u3;
                ldm_x4(t0, t1, t2, t3, Bh + off);
                ldm_x4(u0, u1, u2, u3, Bl + off);
#pragma unroll
                for (int ms = 0; ms < 2; ms++) {
                    mma16816(acc[ms][2 * g],     ah[ms], t0, t2);
                    mma16816(acc[ms][2 * g + 1], ah[ms], t1, t3);
                    mma16816(acc[ms][2 * g],     al[ms], t0, t2);
                    mma16816(acc[ms][2 * g + 1], al[ms], t1, t3);
                    mma16816(acc[ms][2 * g],     ah[ms], u0, u2);
                    mma16816(acc[ms][2 * g + 1], ah[ms], u1, u3);
                }
            }
        }
        __syncthreads();
    }

    // ---- stage [n][m=256] fp32 in smem (pitch 260) ----
    float* sepi = (float*)smc;
    const int em = mw * 32 + (lane >> 2);
    const int ecol = (lane & 3) * 2;
#pragma unroll
    for (int ms = 0; ms < 2; ms++) {
        int m = em + ms * 16;
#pragma unroll
        for (int g = 0; g < NG; g++) {
            int nb = nw * NW + g * 16 + ecol;
            sepi[nb * 260 + m]           = acc[ms][2 * g][0];
            sepi[(nb + 1) * 260 + m]     = acc[ms][2 * g][1];
            sepi[nb * 260 + m + 8]       = acc[ms][2 * g][2];
            sepi[(nb + 1) * 260 + m + 8] = acc[ms][2 * g][3];
            int nb2 = nb + 8;
            sepi[nb2 * 260 + m]           = acc[ms][2 * g + 1][0];
            sepi[(nb2 + 1) * 260 + m]     = acc[ms][2 * g + 1][1];
            sepi[nb2 * 260 + m + 8]       = acc[ms][2 * g + 1][2];
            sepi[(nb2 + 1) * 260 + m + 8] = acc[ms][2 * g + 1][3];
        }
    }
    __syncthreads();

    if (EPI == 0) {
#pragma unroll
        for (int j = 0; j < NT / 8; j++) {
            int lin = j * 512 + tid;           // over NT*64 float4s
            int n = lin >> 6;
            int seg = lin & 63;
            float4 v = *(float4*)(sepi + n * 260 + seg * 4);
            float bz = bias ? bias[oc0 + n] : 0.f;
            v.x += bz; v.y += bz; v.z += bz; v.w += bz;
            *(float4*)(out + (((size_t)(b * NTOT + oc0 + n)) << 16) + sb + seg * 4) = v;
        }
    } else {
        // NHWC fp32 + bias (NT == 64)
#pragma unroll
        for (int j = 0; j < 8; j++) {
            int lin = j * 512 + tid;           // 0..4095
            int m = lin >> 4;
            int cq = lin & 15;
            float4 v;
            v.x = sepi[(cq * 4 + 0) * 260 + m] + bias[cq * 4 + 0];
            v.y = sepi[(cq * 4 + 1) * 260 + m] + bias[cq * 4 + 1];
            v.z = sepi[(cq * 4 + 2) * 260 + m] + bias[cq * 4 + 2];
            v.w = sepi[(cq * 4 + 3) * 260 + m] + bias[cq * 4 + 3];
            *(float4*)(out + ((size_t)(b * 65536 + sb + m)) * 64 + cq * 4) = v;
        }
    }

    if (red) {
        float* sred = sepi + NT * 260;
        int n = tid >> 3, part = tid & 7;      // NT==64: 64 ch x 8 parts of 32
        float bz = bias ? bias[oc0 + n] : 0.f;
        float s1 = 0.f, s2 = 0.f;
        const float* rowp = sepi + n * 260 + part * 32;
#pragma unroll
        for (int j = 0; j < 32; j++) {
            float v = rowp[j] + bz;
            s1 += v;
            s2 = fmaf(v, v, s2);
        }
        sred[(0 * 64 + n) * 8 + part] = s1;
        sred[(1 * 64 + n) * 8 + part] = s2;
        __syncthreads();
        if (tid < 128) {
            int which = tid >> 6, n2 = tid & 63;
            const float* pr = sred + (which * 64 + n2) * 8;
            float s = 0.f;
#pragma unroll
            for (int j = 0; j < 8; j++) s += pr[j];
            atomicAdd(red + which * 64 + oc0 + n2, s);
        }
    }
}

// ================= deformable gather + NHWC hi/lo convert =================
__global__ void __launch_bounds__(256)
gathercvt_k(const float* __restrict__ x2, const float* __restrict__ up,
            const float* __restrict__ offs,
            __nv_bfloat16* __restrict__ oh, __nv_bfloat16* __restrict__ ol)
{
    __shared__ float s[128][33];
    const int s0 = blockIdx.x * 32;
    const int b = blockIdx.y;
    const int tid = threadIdx.x;
    const int px = tid & 31;
    const int hw = s0 + px;
    const int h = hw >> 8;
    const int w = hw & 255;
#pragma unroll 4
    for (int c = tid >> 5; c < 128; c += 8) {
        const float* src = (c < 64) ? x2 + (b * 64 + c) * HWSZ
                                    : up + (b * 64 + (c - 64)) * HWSZ;
        int obase = b * C256 * HWSZ + c * 2 * HWSZ + h * (2 * WW) + 2 * w;
        float oy = offs[obase];
        float ox = offs[obase + 1];
        float cy = fminf(fmaxf(oy + (float)h, 0.f), 255.f);
        float cx = fminf(fmaxf(ox + (float)w, 0.f), 255.f);
        float y0f = floorf(cy), x0f = floorf(cx);
        int y0 = (int)y0f;
        int x0 = (int)x0f;
        int y1 = (int)ceilf(cy);
        int x1 = (int)ceilf(cx);
        float v00 = src[y0 * WW + x0];
        float v10 = src[y1 * WW + x0];
        float v01 = src[y0 * WW + x1];
        float v11 = src[y1 * WW + x1];
        float wy = cy - y0f, wx = cx - x0f;
        float vt = v00 + (v10 - v00) * wy;
        float vb = v01 + (v11 - v01) * wy;
        s[c][px] = vt + (vb - vt) * wx;
    }
    __syncthreads();
#pragma unroll 4
    for (int e = tid; e < 32 * 128; e += 256) {
        int p = e >> 7, c = e & 127;
        float v = s[c][p];
        __nv_bfloat16 hh = __float2bfloat16(v);
        float lo = v - __bfloat162float(hh);
        size_t idx = ((size_t)(b * HWSZ + s0 + p)) * 128 + c;
        oh[idx] = hh;
        ol[idx] = __float2bfloat16(lo);
    }
}

// ================= small kernels =================
__global__ void zero_red_k() { g_red[threadIdx.x] = 0.f; }

__global__ void bnfin_k(const float* __restrict__ red,
                        const float* __restrict__ gamma, const float* __restrict__ beta,
                        float* __restrict__ ab)
{
    int c = threadIdx.x;
    const float invn = 1.f / 131072.f;
    float m = red[c] * invn;
    float var = fmaf(-m, m, red[64 + c] * invn);
    float a = gamma[c] * rsqrtf(var + 1e-5f);
    ab[c] = a;
    ab[64 + c] = fmaf(-m, a, beta[c]);
}

__global__ void __launch_bounds__(256)
afsplit_k(const float* __restrict__ in, const float* __restrict__ ab,
          __nv_bfloat16* __restrict__ oh, __nv_bfloat16* __restrict__ ol)
{
    int i4 = blockIdx.x * 256 + threadIdx.x;
    int c0 = (i4 & 15) * 4;
    float4 v = *(const float4*)(in + (size_t)i4 * 4);
    float vv[4] = {v.x, v.y, v.z, v.w};
    unsigned short hs[4], ls[4];
#pragma unroll
    for (int j = 0; j < 4; j++) {
        int c = c0 + j;
        float y = fmaxf(fmaf(vv[j], __ldg(ab + c), __ldg(ab + 64 + c)), 0.f);
        __nv_bfloat16 hb = __float2bfloat16(y);
        float lo = y - __bfloat162float(hb);
        __nv_bfloat16 lb = __float2bfloat16(lo);
        hs[j] = *(unsigned short*)&hb;
        ls[j] = *(unsigned short*)&lb;
    }
    *(uint2*)((unsigned short*)oh + (size_t)i4 * 4) = *(uint2*)hs;
    *(uint2*)((unsigned short*)ol + (size_t)i4 * 4) = *(uint2*)ls;
}

__global__ void __launch_bounds__(256)
bnrelu_out_k(const float* __restrict__ buf, const float* __restrict__ ab,
             float* __restrict__ out)
{
    int i4 = blockIdx.x * 256 + threadIdx.x;
    int c = (i4 >> 14) & 63;
    float a = __ldg(ab + c), bz = __ldg(ab + 64 + c);
    float4 v = *(const float4*)(buf + (size_t)i4 * 4);
    v.x = fmaxf(fmaf(v.x, a, bz), 0.f);
    v.y = fmaxf(fmaf(v.y, a, bz), 0.f);
    v.z = fmaxf(fmaf(v.z, a, bz), 0.f);
    v.w = fmaxf(fmaf(v.w, a, bz), 0.f);
    *(float4*)(out + (size_t)i4 * 4) = v;
}

// ================= launch =================
extern "C" void kernel_launch(void* const* d_in, const int* in_sizes, int n_in,
                              void* d_out, int out_size)
{
    const float* x1   = (const float*)d_in[0];
    const float* x2   = (const float*)d_in[1];
    const float* up_w = (const float*)d_in[2];
    const float* up_b = (const float*)d_in[3];
    const float* offw = (const float*)d_in[4];
    const float* c1w  = (const float*)d_in[5];
    const float* c1b  = (const float*)d_in[6];
    const float* g1   = (const float*)d_in[7];
    const float* b1   = (const float*)d_in[8];
    const float* c2w  = (const float*)d_in[9];
    const float* c2b  = (const float*)d_in[10];
    const float* g2   = (const float*)d_in[11];
    const float* b2   = (const float*)d_in[12];
    float* outp = (float*)d_out;

    float *p_up, *p_off, *p_h1raw, *p_b2, *p_red, *p_ab1, *p_ab2;
    cudaGetSymbolAddress((void**)&p_up,    g_up);
    cudaGetSymbolAddress((void**)&p_off,   g_off);
    cudaGetSymbolAddress((void**)&p_h1raw, g_h1raw);
    cudaGetSymbolAddress((void**)&p_b2,    g_b2);
    cudaGetSymbolAddress((void**)&p_red,   g_red);
    cudaGetSymbolAddress((void**)&p_ab1,   g_ab1);
    cudaGetSymbolAddress((void**)&p_ab2,   g_ab2);
    __nv_bfloat16 *p_x1_h, *p_x1_l, *p_cat_h, *p_cat_l, *p_xd_h, *p_xd_l, *p_h1_h, *p_h1_l;
    __nv_bfloat16 *p_wo_h, *p_wo_l, *p_w1_h, *p_w1_l, *p_w2_h, *p_w2_l, *p_wu_h, *p_wu_l;
    cudaGetSymbolAddress((void**)&p_x1_h, g_x1_h);
    cudaGetSymbolAddress((void**)&p_x1_l, g_x1_l);
    cudaGetSymbolAddress((void**)&p_cat_h, g_cat_h);
    cudaGetSymbolAddress((void**)&p_cat_l, g_cat_l);
    cudaGetSymbolAddress((void**)&p_xd_h, g_xd_h);
    cudaGetSymbolAddress((void**)&p_xd_l, g_xd_l);
    cudaGetSymbolAddress((void**)&p_h1_h, g_h1_h);
    cudaGetSymbolAddress((void**)&p_h1_l, g_h1_l);
    cudaGetSymbolAddress((void**)&p_wo_h, g_wo_h);
    cudaGetSymbolAddress((void**)&p_wo_l, g_wo_l);
    cudaGetSymbolAddress((void**)&p_w1_h, g_w1_h);
    cudaGetSymbolAddress((void**)&p_w1_l, g_w1_l);
    cudaGetSymbolAddress((void**)&p_w2_h, g_w2_h);
    cudaGetSymbolAddress((void**)&p_w2_l, g_w2_l);
    cudaGetSymbolAddress((void**)&p_wu_h, g_wu_h);
    cudaGetSymbolAddress((void**)&p_wu_l, g_wu_l);

    const int smem_off = 2 * (65536 + 128 * 256) + 1024;  // 197632
    const int smem_c   = 2 * (65536 + 64 * 256) + 1024;   // 164864
    const int smem_up  = 49152 + 1024;
    cudaFuncSetAttribute(convmma_k<256, 2, 128, 0>, cudaFuncAttributeMaxDynamicSharedMemorySize, smem_off);
    cudaFuncSetAttribute(convmma_k<64, 2, 64, 1>,   cudaFuncAttributeMaxDynamicSharedMemorySize, smem_c);
    cudaFuncSetAttribute(convmma_k<64, 1, 64, 0>,   cudaFuncAttributeMaxDynamicSharedMemorySize, smem_c);
    cudaFuncSetAttribute(upmma_k, cudaFuncAttributeMaxDynamicSharedMemorySize, smem_up);

    // 0) zero stats + weight prep
    zero_red_k<<<1, 256>>>();
    wprep_k<<<(256 * 128 * 9 + 255) / 256, 256>>>(offw, p_wo_h, p_wo_l, 256, 128);
    wprep_k<<<(64 * 128 * 9 + 255) / 256, 256>>>(c1w, p_w1_h, p_w1_l, 64, 128);
    wprep_k<<<(64 * 64 * 9 + 255) / 256, 256>>>(c2w, p_w2_h, p_w2_l, 64, 64);
    upwprep_k<<<64, 256>>>(up_w, p_wu_h, p_wu_l);

    // 1) x1 -> NHWC hi/lo, upconv via mma
    tc_k<64, 0, 16384><<<dim3(512, 2), 256>>>(x1, nullptr, p_x1_h, p_x1_l);
    upmma_k<<<dim3(256, 4), 256, smem_up>>>(p_x1_h, p_x1_l, p_wu_h, p_wu_l, up_b, p_up);

    // 2) concat -> NHWC bf16 hi/lo
    tc_k<128, 1, 65536><<<dim3(2048, 2), 256>>>(x2, p_up, p_cat_h, p_cat_l);

    // 3) offset conv -> g_off NCHW fp32 (no bias, no stats)
    convmma_k<256, 2, 128, 0><<<dim3(512, 2), 512, smem_off>>>(
        p_cat_h, p_cat_l, p_wo_h, p_wo_l, nullptr, p_off, nullptr);

    // 4) gather + NHWC hi/lo
    gathercvt_k<<<dim3(2048, 2), 256>>>(x2, p_up, p_off, p_xd_h, p_xd_l);

    // 5) conv1 -> NHWC fp32 + fused BN1 stats
    convmma_k<64, 2, 64, 1><<<dim3(512, 1), 512, smem_c>>>(
        p_xd_h, p_xd_l, p_w1_h, p_w1_l, c1b, p_h1raw, p_red);
    bnfin_k<<<1, 64>>>(p_red, g1, b1, p_ab1);

    // 6) BN1 affine + relu + split
    afsplit_k<<<8192, 256>>>(p_h1raw, p_ab1, p_h1_h, p_h1_l);

    // 7) conv2 -> NCHW fp32 + fused BN2 stats
    convmma_k<64, 1, 64, 0><<<dim3(512, 1), 512, smem_c>>>(
        p_h1_h, p_h1_l, p_w2_h, p_w2_l, c2b, p_b2, p_red + 128);
    bnfin_k<<<1, 64>>>(p_red + 128, g2, b2, p_ab2);

    // 8) final BN+ReLU
    bnrelu_out_k<<<8192, 256>>>(p_b2, p_ab2, outp);
}

// round 7
// speedup vs baseline: 1.2949x; 1.1848x over previous
#include <cuda_runtime.h>
#include <cuda_bf16.h>
#include <cuda_fp16.h>
#include <math.h>
#include <stdint.h>

#define HH 256
#define WW 256
#define HWSZ 65536
#define BB 2
#define C64 64
#define C128 128
#define C256 256

#define SW128(off) ((off) ^ (((off) >> 3) & 0x70))

__device__ __forceinline__ uint32_t smem_u32(const void* p) {
    uint32_t a;
    asm("{ .reg .u64 t; cvta.to.shared.u64 t, %1; cvt.u32.u64 %0, t; }" : "=r"(a) : "l"(p));
    return a;
}
__device__ __forceinline__ void cpa16(uint32_t dst, const void* src, int sz) {
    asm volatile("cp.async.cg.shared.global [%0], [%1], 16, %2;"
                 :: "r"(dst), "l"(src), "r"(sz) : "memory");
}
__device__ __forceinline__ void cpa_commit() {
    asm volatile("cp.async.commit_group;" ::: "memory");
}
template<int N>
__device__ __forceinline__ void cpa_wait() {
    asm volatile("cp.async.wait_group %0;" :: "n"(N) : "memory");
}
__device__ __forceinline__ void ldm_x4(uint32_t& r0, uint32_t& r1, uint32_t& r2, uint32_t& r3,
                                       uint32_t addr) {
    asm volatile("ldmatrix.sync.aligned.m8n8.x4.shared.b16 {%0,%1,%2,%3}, [%4];"
                 : "=r"(r0), "=r"(r1), "=r"(r2), "=r"(r3) : "r"(addr));
}
// bf16 mma (upconv path)
__device__ __forceinline__ void mma_bf16(float* c, const uint32_t* a, uint32_t b0, uint32_t b1) {
    asm volatile("mma.sync.aligned.m16n8k16.row.col.f32.bf16.bf16.f32 "
                 "{%0,%1,%2,%3}, {%4,%5,%6,%7}, {%8,%9}, {%0,%1,%2,%3};"
                 : "+f"(c[0]), "+f"(c[1]), "+f"(c[2]), "+f"(c[3])
                 : "r"(a[0]), "r"(a[1]), "r"(a[2]), "r"(a[3]), "r"(b0), "r"(b1));
}
// fp16 mma (conv path)
__device__ __forceinline__ void mma_f16(float* c, const uint32_t* a, uint32_t b0, uint32_t b1) {
    asm volatile("mma.sync.aligned.m16n8k16.row.col.f32.f16.f16.f32 "
                 "{%0,%1,%2,%3}, {%4,%5,%6,%7}, {%8,%9}, {%0,%1,%2,%3};"
                 : "+f"(c[0]), "+f"(c[1]), "+f"(c[2]), "+f"(c[3])
                 : "r"(a[0]), "r"(a[1]), "r"(a[2]), "r"(a[3]), "r"(b0), "r"(b1));
}

// ================= scratch (device globals) =================
__device__ float g_up   [BB * C64 * HWSZ];
__device__ float g_off  [BB * C256 * HWSZ];
__device__ float g_h1raw[BB * HWSZ * C64];
__device__ float g_b2   [BB * C64 * HWSZ];
__device__ float g_red[256];
__device__ float g_ab1[128];
__device__ float g_ab2[128];
__device__ __nv_bfloat16 g_x1_h[BB * 16384 * C64];
__device__ __nv_bfloat16 g_x1_l[BB * 16384 * C64];
__device__ __nv_bfloat16 g_wu_h[C256 * 64];
__device__ __nv_bfloat16 g_wu_l[C256 * 64];
__device__ __half g_cat [BB * HWSZ * C128];     // offconv A (fp16 single)
__device__ __half g_xd  [BB * HWSZ * C128];     // conv1 A (fp16 single)
__device__ __half g_h1  [BB * HWSZ * C64];      // conv2 A (fp16 single)
__device__ __half g_wo  [18 * C256 * 64];       // offconv B (single)
__device__ __half g_w1h [18 * C64 * 64];        // conv1 B hi
__device__ __half g_w1l [18 * C64 * 64];        // conv1 B lo
__device__ __half g_w2h [9 * C64 * 64];
__device__ __half g_w2l [9 * C64 * 64];

// ================= weight prep =================
// single-plane fp16: [kc][o][cc]
__global__ void wprep_f16_k(const float* __restrict__ w, __half* __restrict__ wh,
                            int N, int CIN)
{
    int i = blockIdx.x * blockDim.x + threadIdx.x;
    if (i >= N * CIN * 9) return;
    int t  = i % 9;
    int ci = (i / 9) % CIN;
    int o  = i / (9 * CIN);
    int q = ci >> 6, cc = ci & 63;
    int kc = t * (CIN >> 6) + q;
    wh[(kc * N + o) * 64 + cc] = __float2half_rn(w[i]);
}
// hi/lo fp16
__global__ void wprep_f16x2_k(const float* __restrict__ w, __half* __restrict__ wh,
                              __half* __restrict__ wl, int N, int CIN)
{
    int i = blockIdx.x * blockDim.x + threadIdx.x;
    if (i >= N * CIN * 9) return;
    int t  = i % 9;
    int ci = (i / 9) % CIN;
    int o  = i / (9 * CIN);
    int q = ci >> 6, cc = ci & 63;
    int kc = t * (CIN >> 6) + q;
    float v = w[i];
    __half h = __float2half_rn(v);
    float lo = v - __half2float(h);
    int dst = (kc * N + o) * 64 + cc;
    wh[dst] = h;
    wl[dst] = __float2half_rn(lo);
}
// upconv weights (I,O,2,2) -> bf16 hi/lo [n][cc]
__global__ void upwprep_k(const float* __restrict__ w, __nv_bfloat16* __restrict__ wh,
                          __nv_bfloat16* __restrict__ wl)
{
    int s = blockIdx.x * blockDim.x + threadIdx.x;
    if (s >= 64 * 256) return;
    int n = s & 255;
    int cc = s >> 8;
    float v = w[s];
    __nv_bfloat16 h = __float2bfloat16(v);
    float lo = v - __bfloat162float(h);
    wh[n * 64 + cc] = h;
    wl[n * 64 + cc] = __float2bfloat16(lo);
}

// ================= x1 NCHW -> NHWC bf16 hi/lo (upconv A) =================
__global__ void __launch_bounds__(256)
tc_x1_k(const float* __restrict__ in0,
        __nv_bfloat16* __restrict__ oh, __nv_bfloat16* __restrict__ ol)
{
    __shared__ float s[64][33];
    const int s0 = blockIdx.x * 32;
    const int b = blockIdx.y;
    const int tid = threadIdx.x;
    const int px = tid & 31;
#pragma unroll 4
    for (int c = tid >> 5; c < 64; c += 8)
        s[c][px] = in0[(b * 64 + c) * 16384 + s0 + px];
    __syncthreads();
#pragma unroll 4
    for (int e = tid; e < 32 * 64; e += 256) {
        int p = e >> 6, c = e & 63;
        float v = s[c][p];
        __nv_bfloat16 h = __float2bfloat16(v);
        float lo = v - __bfloat162float(h);
        size_t idx = ((size_t)(b * 16384 + s0 + p)) * 64 + c;
        oh[idx] = h;
        ol[idx] = __float2bfloat16(lo);
    }
}

// ================= concat -> NHWC fp16 single (offconv A) =================
__global__ void __launch_bounds__(256)
tc_cat_k(const float* __restrict__ x2, const float* __restrict__ up,
         __half* __restrict__ oc)
{
    __shared__ float s[128][33];
    const int s0 = blockIdx.x * 32;
    const int b = blockIdx.y;
    const int tid = threadIdx.x;
    const int px = tid & 31;
#pragma unroll 4
    for (int c = tid >> 5; c < 128; c += 8) {
        const float* src = (c < 64) ? x2 + (b * 64 + c) * HWSZ
                                    : up + (b * 64 + (c - 64)) * HWSZ;
        s[c][px] = src[s0 + px];
    }
    __syncthreads();
#pragma unroll 4
    for (int e = tid; e < 32 * 128; e += 256) {
        int p = e >> 7, c = e & 127;
        size_t idx = ((size_t)(b * HWSZ + s0 + p)) * 128 + c;
        oc[idx] = __float2half_rn(s[c][p]);
    }
}

// ================= upconv via mma (bf16x3, unchanged) =================
__global__ void __launch_bounds__(256, 2)
upmma_k(const __nv_bfloat16* __restrict__ ah_g, const __nv_bfloat16* __restrict__ al_g,
        const __nv_bfloat16* __restrict__ bh_g, const __nv_bfloat16* __restrict__ bl_g,
        const float* __restrict__ upb, float* __restrict__ up)
{
    extern __shared__ char dsm[];
    constexpr int A_H = 0, A_L = 16384, B_H = 32768, B_L = 40960;
    uint32_t raw = smem_u32(dsm);
    uint32_t base = (raw + 1023u) & ~1023u;
    char* smc = dsm + (base - raw);
    const int tid = threadIdx.x;
    const int wid = tid >> 5;
    const int lane = tid & 31;

    const int p0 = blockIdx.x * 128;
    const int b  = p0 >> 14;
    const int sb = p0 & 16383;
    const int y0 = sb >> 7;
    const int oc0 = blockIdx.y * 64;

#pragma unroll
    for (int it = 0; it < 4; it++) {
        int idx = it * 256 + tid;
        int m = idx >> 3, ch = idx & 7;
        size_t gi = ((size_t)(p0 + m)) * 64 + ch * 8;
        uint32_t sw = SW128(m * 128 + ch * 16);
        cpa16(base + A_H + sw, ah_g + gi, 16);
        cpa16(base + A_L + sw, al_g + gi, 16);
    }
#pragma unroll
    for (int it = 0; it < 2; it++) {
        int idx = it * 256 + tid;
        int o = idx >> 3, ch = idx & 7;
        size_t gi = ((size_t)(oc0 + o)) * 64 + ch * 8;
        uint32_t sw = SW128(o * 128 + ch * 16);
        cpa16(base + B_H + sw, bh_g + gi, 16);
        cpa16(base + B_L + sw, bl_g + gi, 16);
    }
    cpa_commit();
    cpa_wait<0>();
    __syncthreads();

    float acc[8][4];
#pragma unroll
    for (int g = 0; g < 8; g++)
#pragma unroll
        for (int j = 0; j < 4; j++) acc[g][j] = 0.f;

    const uint32_t Ah = base + A_H, Al = base + A_L;
    const uint32_t Bh = base + B_H, Bl = base + B_L;
    const int arow = wid * 16 + (lane & 15);
    const int nrow = lane & 15;
    const int chalf = (lane >> 4) * 16;
#pragma unroll
    for (int kk = 0; kk < 4; kk++) {
        const int cb = chalf + kk * 32;
        uint32_t ah[4], al[4];
        ldm_x4(ah[0], ah[1], ah[2], ah[3], Ah + SW128(arow * 128 + cb));
        ldm_x4(al[0], al[1], al[2], al[3], Al + SW128(arow * 128 + cb));
#pragma unroll
        for (int g = 0; g < 4; g++) {
            uint32_t off = SW128((g * 16 + nrow) * 128 + cb);
            uint32_t t0, t1, t2, t3, u0, u1, u2, u3;
            ldm_x4(t0, t1, t2, t3, Bh + off);
            ldm_x4(u0, u1, u2, u3, Bl + off);
            mma_bf16(acc[2 * g],     ah, t0, t2);
            mma_bf16(acc[2 * g + 1], ah, t1, t3);
            mma_bf16(acc[2 * g],     al, t0, t2);
            mma_bf16(acc[2 * g + 1], al, t1, t3);
            mma_bf16(acc[2 * g],     ah, u0, u2);
            mma_bf16(acc[2 * g + 1], ah, u1, u3);
        }
    }
    __syncthreads();

    float* sepi = (float*)smc;
    const int em = wid * 16 + (lane >> 2);
    const int en = (lane & 3) * 2;
#pragma unroll
    for (int g = 0; g < 8; g++) {
        int n0 = g * 8 + en;
        sepi[n0 * 132 + em]           = acc[g][0];
        sepi[(n0 + 1) * 132 + em]     = acc[g][1];
        sepi[n0 * 132 + em + 8]       = acc[g][2];
        sepi[(n0 + 1) * 132 + em + 8] = acc[g][3];
    }
    __syncthreads();
#pragma unroll 4
    for (int j = 0; j < 32; j++) {
        int lin = j * 256 + tid;
        int n = lin >> 7, m = lin & 127;
        int ng = oc0 + n;
        int o = ng >> 2, k = (ng >> 1) & 1, l = ng & 1;
        float v = sepi[n * 132 + m] + upb[o];
        up[((size_t)(b * 64 + o) << 16) + (2 * y0 + k) * 256 + 2 * m + l] = v;
    }
}

// ================= fp16 implicit-GEMM 3x3 conv, M=256, 512 thr =================
// A single fp16 plane. TWOPASS: B hi/lo (2 MMA passes) else B single (1 pass).
// EPI 0: NCHW fp32 (+bias/stats opt). EPI 1: NHWC fp32 + bias + stats.
template<int NTOT, int CINQ, int NT, int EPI, int TWOPASS>
__global__ void __launch_bounds__(512)
convmma_k(const __half* __restrict__ a_g,
          const __half* __restrict__ bh_g, const __half* __restrict__ bl_g,
          const float* __restrict__ bias, float* __restrict__ out, float* __restrict__ red)
{
    extern __shared__ char dsm[];
    constexpr int CCH = CINQ * 64;
    constexpr int NC  = CINQ * 9;
    constexpr int NW  = NT / 2;
    constexpr int NG  = NW / 16;
    constexpr int B_OFF = 32768;                       // A: 256 rows x 128B
    constexpr int STAGE = 32768 + NT * 128 * (1 + TWOPASS);

    uint32_t raw = smem_u32(dsm);
    uint32_t base = (raw + 1023u) & ~1023u;
    char* smc = dsm + (base - raw);
    const int tid = threadIdx.x;
    const int wid = tid >> 5;
    const int lane = tid & 31;
    const int mw = wid & 7;
    const int nw = wid >> 3;

    const int b  = blockIdx.x >> 8;
    const int y0 = blockIdx.x & 255;
    const int sb = y0 << 8;
    const int oc0 = blockIdx.y * NT;

    auto stage = [&](int chunk, int buf) {
        const int t = chunk / CINQ;
        const int q = chunk - t * CINQ;
        const int ky = t / 3 - 1;
        const int kx = t % 3 - 1;
        const uint32_t sbase = base + buf * STAGE;
        const int yy = y0 + ky;
        const bool yin = (unsigned)yy < 256u;
#pragma unroll
        for (int it = 0; it < 4; it++) {
            int idx = it * 512 + tid;          // 0..2047
            int m = idx >> 3, ch = idx & 7;
            int xx = m + kx;
            bool inb = yin && ((unsigned)xx < 256u);
            size_t gi = (((size_t)b << 16) + (yy << 8) + xx) * CCH + q * 64 + ch * 8;
            if (!inb) gi = 0;
            cpa16(sbase + SW128(m * 128 + ch * 16), a_g + gi, inb ? 16 : 0);
        }
        for (int idx = tid; idx < NT * 8; idx += 512) {
            int o = idx >> 3, ch = idx & 7;
            size_t gi = ((size_t)chunk * NTOT + oc0 + o) * 64 + ch * 8;
            uint32_t sw = SW128(o * 128 + ch * 16);
            cpa16(sbase + B_OFF + sw, bh_g + gi, 16);
            if (TWOPASS) cpa16(sbase + B_OFF + NT * 128 + sw, bl_g + gi, 16);
        }
        cpa_commit();
    };

    float acc[2][NW / 8][4];
#pragma unroll
    for (int ms = 0; ms < 2; ms++)
#pragma unroll
        for (int g = 0; g < NW / 8; g++)
#pragma unroll
            for (int j = 0; j < 4; j++) acc[ms][g][j] = 0.f;

    stage(0, 0);

    const int chalf = (lane >> 4) * 16;
    const int nrow = lane & 15;
    const int arowb = mw * 32 + (lane & 15);

#pragma unroll 1
    for (int chunk = 0; chunk < NC; chunk++) {
        if (chunk + 1 < NC) {
            stage(chunk + 1, (chunk + 1) & 1);
            cpa_wait<1>();
        } else {
            cpa_wait<0>();
        }
        __syncthreads();

        const uint32_t sbase = base + (chunk & 1) * STAGE;
        const uint32_t Ab = sbase;
        const uint32_t Bh = sbase + B_OFF, Bl = sbase + B_OFF + NT * 128;

#pragma unroll
        for (int kk = 0; kk < 4; kk++) {
            const int cb = chalf + kk * 32;
            uint32_t ah[2][4];
#pragma unroll
            for (int ms = 0; ms < 2; ms++) {
                int r = arowb + ms * 16;
                ldm_x4(ah[ms][0], ah[ms][1], ah[ms][2], ah[ms][3], Ab + SW128(r * 128 + cb));
            }
#pragma unroll
            for (int g = 0; g < NG; g++) {
                uint32_t off = SW128((nw * NW + g * 16 + nrow) * 128 + cb);
                uint32_t t0, t1, t2, t3;
                ldm_x4(t0, t1, t2, t3, Bh + off);
#pragma unroll
                for (int ms = 0; ms < 2; ms++) {
                    mma_f16(acc[ms][2 * g],     ah[ms], t0, t2);
                    mma_f16(acc[ms][2 * g + 1], ah[ms], t1, t3);
                }
                if (TWOPASS) {
                    uint32_t u0, u1, u2, u3;
                    ldm_x4(u0, u1, u2, u3, Bl + off);
#pragma unroll
                    for (int ms = 0; ms < 2; ms++) {
                        mma_f16(acc[ms][2 * g],     ah[ms], u0, u2);
                        mma_f16(acc[ms][2 * g + 1], ah[ms], u1, u3);
                    }
                }
            }
        }
        __syncthreads();
    }

    // ---- stage [n][m=256] fp32 in smem (pitch 260) ----
    float* sepi = (float*)smc;
    const int em = mw * 32 + (lane >> 2);
    const int ecol = (lane & 3) * 2;
#pragma unroll
    for (int ms = 0; ms < 2; ms++) {
        int m = em + ms * 16;
#pragma unroll
        for (int g = 0; g < NG; g++) {
            int nb = nw * NW + g * 16 + ecol;
            sepi[nb * 260 + m]           = acc[ms][2 * g][0];
            sepi[(nb + 1) * 260 + m]     = acc[ms][2 * g][1];
            sepi[nb * 260 + m + 8]       = acc[ms][2 * g][2];
            sepi[(nb + 1) * 260 + m + 8] = acc[ms][2 * g][3];
            int nb2 = nb + 8;
            sepi[nb2 * 260 + m]           = acc[ms][2 * g + 1][0];
            sepi[(nb2 + 1) * 260 + m]     = acc[ms][2 * g + 1][1];
            sepi[nb2 * 260 + m + 8]       = acc[ms][2 * g + 1][2];
            sepi[(nb2 + 1) * 260 + m + 8] = acc[ms][2 * g + 1][3];
        }
    }
    __syncthreads();

    if (EPI == 0) {
#pragma unroll
        for (int j = 0; j < NT / 8; j++) {
            int lin = j * 512 + tid;
            int n = lin >> 6;
            int seg = lin & 63;
            float4 v = *(float4*)(sepi + n * 260 + seg * 4);
            float bz = bias ? bias[oc0 + n] : 0.f;
            v.x += bz; v.y += bz; v.z += bz; v.w += bz;
            *(float4*)(out + (((size_t)(b * NTOT + oc0 + n)) << 16) + sb + seg * 4) = v;
        }
    } else {
#pragma unroll
        for (int j = 0; j < 8; j++) {
            int lin = j * 512 + tid;
            int m = lin >> 4;
            int cq = lin & 15;
            float4 v;
            v.x = sepi[(cq * 4 + 0) * 260 + m] + bias[cq * 4 + 0];
            v.y = sepi[(cq * 4 + 1) * 260 + m] + bias[cq * 4 + 1];
            v.z = sepi[(cq * 4 + 2) * 260 + m] + bias[cq * 4 + 2];
            v.w = sepi[(cq * 4 + 3) * 260 + m] + bias[cq * 4 + 3];
            *(float4*)(out + ((size_t)(b * 65536 + sb + m)) * 64 + cq * 4) = v;
        }
    }

    if (red) {
        float* sred = sepi + NT * 260;
        int n = tid >> 3, part = tid & 7;
        float bz = bias ? bias[oc0 + n] : 0.f;
        float s1 = 0.f, s2 = 0.f;
        const float* rowp = sepi + n * 260 + part * 32;
#pragma unroll
        for (int j = 0; j < 32; j++) {
            float v = rowp[j] + bz;
            s1 += v;
            s2 = fmaf(v, v, s2);
        }
        sred[(0 * 64 + n) * 8 + part] = s1;
        sred[(1 * 64 + n) * 8 + part] = s2;
        __syncthreads();
        if (tid < 128) {
            int which = tid >> 6, n2 = tid & 63;
            const float* pr = sred + (which * 64 + n2) * 8;
            float s = 0.f;
#pragma unroll
            for (int j = 0; j < 8; j++) s += pr[j];
            atomicAdd(red + which * 64 + oc0 + n2, s);
        }
    }
}

// ================= deformable gather -> xd NHWC fp16 single =================
__global__ void __launch_bounds__(256)
gathercvt_k(const float* __restrict__ x2, const float* __restrict__ up,
            const float* __restrict__ offs, __half* __restrict__ oc)
{
    __shared__ float s[128][33];
    const int s0 = blockIdx.x * 32;
    const int b = blockIdx.y;
    const int tid = threadIdx.x;
    const int px = tid & 31;
    const int hw = s0 + px;
    const int h = hw >> 8;
    const int w = hw & 255;
#pragma unroll 4
    for (int c = tid >> 5; c < 128; c += 8) {
        const float* src = (c < 64) ? x2 + (b * 64 + c) * HWSZ
                                    : up + (b * 64 + (c - 64)) * HWSZ;
        int obase = b * C256 * HWSZ + c * 2 * HWSZ + h * (2 * WW) + 2 * w;
        float oy = offs[obase];
        float ox = offs[obase + 1];
        float cy = fminf(fmaxf(oy + (float)h, 0.f), 255.f);
        float cx = fminf(fmaxf(ox + (float)w, 0.f), 255.f);
        float y0f = floorf(cy), x0f = floorf(cx);
        int y0 = (int)y0f;
        int x0 = (int)x0f;
        int y1 = (int)ceilf(cy);
        int x1 = (int)ceilf(cx);
        float v00 = src[y0 * WW + x0];
        float v10 = src[y1 * WW + x0];
        float v01 = src[y0 * WW + x1];
        float v11 = src[y1 * WW + x1];
        float wy = cy - y0f, wx = cx - x0f;
        float vt = v00 + (v10 - v00) * wy;
        float vb = v01 + (v11 - v01) * wy;
        s[c][px] = vt + (vb - vt) * wx;
    }
    __syncthreads();
#pragma unroll 4
    for (int e = tid; e < 32 * 128; e += 256) {
        int p = e >> 7, c = e & 127;
        size_t idx = ((size_t)(b * HWSZ + s0 + p)) * 128 + c;
        oc[idx] = __float2half_rn(s[c][p]);
    }
}

// ================= small kernels =================
__global__ void zero_red_k() { g_red[threadIdx.x] = 0.f; }

__global__ void bnfin_k(const float* __restrict__ red,
                        const float* __restrict__ gamma, const float* __restrict__ beta,
                        float* __restrict__ ab)
{
    int c = threadIdx.x;
    const float invn = 1.f / 131072.f;
    float m = red[c] * invn;
    float var = fmaf(-m, m, red[64 + c] * invn);
    float a = gamma[c] * rsqrtf(var + 1e-5f);
    ab[c] = a;
    ab[64 + c] = fmaf(-m, a, beta[c]);
}

// NHWC fp32 -> affine+relu -> fp16 single
__global__ void __launch_bounds__(256)
afsplit_k(const float* __restrict__ in, const float* __restrict__ ab,
          __half* __restrict__ oc)
{
    int i4 = blockIdx.x * 256 + threadIdx.x;
    int c0 = (i4 & 15) * 4;
    float4 v = *(const float4*)(in + (size_t)i4 * 4);
    float vv[4] = {v.x, v.y, v.z, v.w};
    unsigned short hs[4];
#pragma unroll
    for (int j = 0; j < 4; j++) {
        int c = c0 + j;
        float y = fmaxf(fmaf(vv[j], __ldg(ab + c), __ldg(ab + 64 + c)), 0.f);
        __half hb = __float2half_rn(y);
        hs[j] = *(unsigned short*)&hb;
    }
    *(uint2*)((unsigned short*)oc + (size_t)i4 * 4) = *(uint2*)hs;
}

__global__ void __launch_bounds__(256)
bnrelu_out_k(const float* __restrict__ buf, const float* __restrict__ ab,
             float* __restrict__ out)
{
    int i4 = blockIdx.x * 256 + threadIdx.x;
    int c = (i4 >> 14) & 63;
    float a = __ldg(ab + c), bz = __ldg(ab + 64 + c);
    float4 v = *(const float4*)(buf + (size_t)i4 * 4);
    v.x = fmaxf(fmaf(v.x, a, bz), 0.f);
    v.y = fmaxf(fmaf(v.y, a, bz), 0.f);
    v.z = fmaxf(fmaf(v.z, a, bz), 0.f);
    v.w = fmaxf(fmaf(v.w, a, bz), 0.f);
    *(float4*)(out + (size_t)i4 * 4) = v;
}

// ================= launch =================
extern "C" void kernel_launch(void* const* d_in, const int* in_sizes, int n_in,
                              void* d_out, int out_size)
{
    const float* x1   = (const float*)d_in[0];
    const float* x2   = (const float*)d_in[1];
    const float* up_w = (const float*)d_in[2];
    const float* up_b = (const float*)d_in[3];
    const float* offw = (const float*)d_in[4];
    const float* c1w  = (const float*)d_in[5];
    const float* c1b  = (const float*)d_in[6];
    const float* g1   = (const float*)d_in[7];
    const float* b1   = (const float*)d_in[8];
    const float* c2w  = (const float*)d_in[9];
    const float* c2b  = (const float*)d_in[10];
    const float* g2   = (const float*)d_in[11];
    const float* b2   = (const float*)d_in[12];
    float* outp = (float*)d_out;

    float *p_up, *p_off, *p_h1raw, *p_b2, *p_red, *p_ab1, *p_ab2;
    cudaGetSymbolAddress((void**)&p_up,    g_up);
    cudaGetSymbolAddress((void**)&p_off,   g_off);
    cudaGetSymbolAddress((void**)&p_h1raw, g_h1raw);
    cudaGetSymbolAddress((void**)&p_b2,    g_b2);
    cudaGetSymbolAddress((void**)&p_red,   g_red);
    cudaGetSymbolAddress((void**)&p_ab1,   g_ab1);
    cudaGetSymbolAddress((void**)&p_ab2,   g_ab2);
    __nv_bfloat16 *p_x1_h, *p_x1_l, *p_wu_h, *p_wu_l;
    cudaGetSymbolAddress((void**)&p_x1_h, g_x1_h);
    cudaGetSymbolAddress((void**)&p_x1_l, g_x1_l);
    cudaGetSymbolAddress((void**)&p_wu_h, g_wu_h);
    cudaGetSymbolAddress((void**)&p_wu_l, g_wu_l);
    __half *p_cat, *p_xd, *p_h1, *p_wo, *p_w1h, *p_w1l, *p_w2h, *p_w2l;
    cudaGetSymbolAddress((void**)&p_cat, g_cat);
    cudaGetSymbolAddress((void**)&p_xd,  g_xd);
    cudaGetSymbolAddress((void**)&p_h1,  g_h1);
    cudaGetSymbolAddress((void**)&p_wo,  g_wo);
    cudaGetSymbolAddress((void**)&p_w1h, g_w1h);
    cudaGetSymbolAddress((void**)&p_w1l, g_w1l);
    cudaGetSymbolAddress((void**)&p_w2h, g_w2h);
    cudaGetSymbolAddress((void**)&p_w2l, g_w2l);

    // smem: offconv NT=128 1-pass: stage 48K x2 = 96K; epi 128*260*4 = 133120 -> 134144
    //       conv NT=64 2-pass: stage 48K x2 = 96K; epi 66560+4096 -> 97280 + align
    const int smem_off = 133120 + 2048;
    const int smem_c   = 98304 + 2048;
    const int smem_up  = 49152 + 1024;
    cudaFuncSetAttribute(convmma_k<256, 2, 128, 0, 0>, cudaFuncAttributeMaxDynamicSharedMemorySize, smem_off);
    cudaFuncSetAttribute(convmma_k<64, 2, 64, 1, 1>,   cudaFuncAttributeMaxDynamicSharedMemorySize, smem_c);
    cudaFuncSetAttribute(convmma_k<64, 1, 64, 0, 1>,   cudaFuncAttributeMaxDynamicSharedMemorySize, smem_c);
    cudaFuncSetAttribute(upmma_k, cudaFuncAttributeMaxDynamicSharedMemorySize, smem_up);

    // 0) zero stats + weight prep
    zero_red_k<<<1, 256>>>();
    wprep_f16_k<<<(256 * 128 * 9 + 255) / 256, 256>>>(offw, p_wo, 256, 128);
    wprep_f16x2_k<<<(64 * 128 * 9 + 255) / 256, 256>>>(c1w, p_w1h, p_w1l, 64, 128);
    wprep_f16x2_k<<<(64 * 64 * 9 + 255) / 256, 256>>>(c2w, p_w2h, p_w2l, 64, 64);
    upwprep_k<<<64, 256>>>(up_w, p_wu_h, p_wu_l);

    // 1) x1 -> NHWC bf16 hi/lo, upconv via bf16x3 mma
    tc_x1_k<<<dim3(512, 2), 256>>>(x1, p_x1_h, p_x1_l);
    upmma_k<<<dim3(256, 4), 256, smem_up>>>(p_x1_h, p_x1_l, p_wu_h, p_wu_l, up_b, p_up);

    // 2) concat -> NHWC fp16
    tc_cat_k<<<dim3(2048, 2), 256>>>(x2, p_up, p_cat);

    // 3) offset conv (fp16, 1-pass) -> g_off NCHW fp32
    convmma_k<256, 2, 128, 0, 0><<<dim3(512, 2), 512, smem_off>>>(
        p_cat, p_wo, nullptr, nullptr, p_off, nullptr);

    // 4) gather -> xd NHWC fp16
    gathercvt_k<<<dim3(2048, 2), 256>>>(x2, p_up, p_off, p_xd);

    // 5) conv1 (fp16 2-pass) -> NHWC fp32 + BN1 stats
    convmma_k<64, 2, 64, 1, 1><<<dim3(512, 1), 512, smem_c>>>(
        p_xd, p_w1h, p_w1l, c1b, p_h1raw, p_red);
    bnfin_k<<<1, 64>>>(p_red, g1, b1, p_ab1);

    // 6) BN1 affine + relu -> fp16
    afsplit_k<<<8192, 256>>>(p_h1raw, p_ab1, p_h1);

    // 7) conv2 (fp16 2-pass) -> NCHW fp32 + BN2 stats
    convmma_k<64, 1, 64, 0, 1><<<dim3(512, 1), 512, smem_c>>>(
        p_h1, p_w2h, p_w2l, c2b, p_b2, p_red + 128);
    bnfin_k<<<1, 64>>>(p_red + 128, g2, b2, p_ab2);

    // 8) final BN+ReLU
    bnrelu_out_k<<<8192, 256>>>(p_b2, p_ab2, outp);
}

// round 9
// speedup vs baseline: 1.9928x; 1.5389x over previous
#include <cuda_runtime.h>
#include <cuda_bf16.h>
#include <cuda_fp16.h>
#include <math.h>
#include <stdint.h>

#define HH 256
#define WW 256
#define HWSZ 65536
#define BB 2
#define C64 64
#define C128 128
#define C256 256

#define SW128(off) ((off) ^ (((off) >> 3) & 0x70))

__device__ __forceinline__ uint32_t smem_u32(const void* p) {
    uint32_t a;
    asm("{ .reg .u64 t; cvta.to.shared.u64 t, %1; cvt.u32.u64 %0, t; }" : "=r"(a) : "l"(p));
    return a;
}
__device__ __forceinline__ void cpa16(uint32_t dst, const void* src, int sz) {
    asm volatile("cp.async.cg.shared.global [%0], [%1], 16, %2;"
                 :: "r"(dst), "l"(src), "r"(sz) : "memory");
}
__device__ __forceinline__ void cpa_commit() {
    asm volatile("cp.async.commit_group;" ::: "memory");
}
template<int N>
__device__ __forceinline__ void cpa_wait() {
    asm volatile("cp.async.wait_group %0;" :: "n"(N) : "memory");
}
__device__ __forceinline__ void ldm_x4(uint32_t& r0, uint32_t& r1, uint32_t& r2, uint32_t& r3,
                                       uint32_t addr) {
    asm volatile("ldmatrix.sync.aligned.m8n8.x4.shared.b16 {%0,%1,%2,%3}, [%4];"
                 : "=r"(r0), "=r"(r1), "=r"(r2), "=r"(r3) : "r"(addr));
}
__device__ __forceinline__ void mma_bf16(float* c, const uint32_t* a, uint32_t b0, uint32_t b1) {
    asm volatile("mma.sync.aligned.m16n8k16.row.col.f32.bf16.bf16.f32 "
                 "{%0,%1,%2,%3}, {%4,%5,%6,%7}, {%8,%9}, {%0,%1,%2,%3};"
                 : "+f"(c[0]), "+f"(c[1]), "+f"(c[2]), "+f"(c[3])
                 : "r"(a[0]), "r"(a[1]), "r"(a[2]), "r"(a[3]), "r"(b0), "r"(b1));
}
__device__ __forceinline__ void mma_f16(float* c, const uint32_t* a, uint32_t b0, uint32_t b1) {
    asm volatile("mma.sync.aligned.m16n8k16.row.col.f32.f16.f16.f32 "
                 "{%0,%1,%2,%3}, {%4,%5,%6,%7}, {%8,%9}, {%0,%1,%2,%3};"
                 : "+f"(c[0]), "+f"(c[1]), "+f"(c[2]), "+f"(c[3])
                 : "r"(a[0]), "r"(a[1]), "r"(a[2]), "r"(a[3]), "r"(b0), "r"(b1));
}

// ================= scratch (device globals) =================
__device__ float g_up   [BB * C64 * HWSZ];
__device__ __half g_off [BB * C256 * HWSZ];
__device__ float g_h1raw[BB * HWSZ * C64];
__device__ float g_b2   [BB * C64 * HWSZ];
__device__ float g_red[256];
__device__ float g_ab1[128];
__device__ float g_ab2[128];
__device__ __nv_bfloat16 g_x1_h[BB * 16384 * C64];
__device__ __nv_bfloat16 g_x1_l[BB * 16384 * C64];
__device__ __nv_bfloat16 g_wu_h[C256 * 64];
__device__ __nv_bfloat16 g_wu_l[C256 * 64];
__device__ __half g_cat [BB * HWSZ * C128];
__device__ __half g_xd  [BB * HWSZ * C128];
__device__ __half g_h1  [BB * HWSZ * C64];
__device__ __half g_wo  [18 * C256 * 64];
__device__ __half g_w1h [18 * C64 * 64];
__device__ __half g_w1l [18 * C64 * 64];
__device__ __half g_w2h [9 * C64 * 64];
__device__ __half g_w2l [9 * C64 * 64];

// ================= weight prep =================
__global__ void wprep_f16_k(const float* __restrict__ w, __half* __restrict__ wh,
                            int N, int CIN)
{
    int i = blockIdx.x * blockDim.x + threadIdx.x;
    if (i >= N * CIN * 9) return;
    int t  = i % 9;
    int ci = (i / 9) % CIN;
    int o  = i / (9 * CIN);
    int q = ci >> 6, cc = ci & 63;
    int kc = t * (CIN >> 6) + q;
    wh[(kc * N + o) * 64 + cc] = __float2half_rn(w[i]);
}
__global__ void wprep_f16x2_k(const float* __restrict__ w, __half* __restrict__ wh,
                              __half* __restrict__ wl, int N, int CIN)
{
    int i = blockIdx.x * blockDim.x + threadIdx.x;
    if (i >= N * CIN * 9) return;
    int t  = i % 9;
    int ci = (i / 9) % CIN;
    int o  = i / (9 * CIN);
    int q = ci >> 6, cc = ci & 63;
    int kc = t * (CIN >> 6) + q;
    float v = w[i];
    __half h = __float2half_rn(v);
    float lo = v - __half2float(h);
    int dst = (kc * N + o) * 64 + cc;
    wh[dst] = h;
    wl[dst] = __float2half_rn(lo);
}
__global__ void upwprep_k(const float* __restrict__ w, __nv_bfloat16* __restrict__ wh,
                          __nv_bfloat16* __restrict__ wl)
{
    int s = blockIdx.x * blockDim.x + threadIdx.x;
    if (s >= 64 * 256) return;
    int n = s & 255;
    int cc = s >> 8;
    float v = w[s];
    __nv_bfloat16 h = __float2bfloat16(v);
    float lo = v - __bfloat162float(h);
    wh[n * 64 + cc] = h;
    wl[n * 64 + cc] = __float2bfloat16(lo);
}

// ================= x1 NCHW -> NHWC bf16 hi/lo =================
__global__ void __launch_bounds__(256)
tc_x1_k(const float* __restrict__ in0,
        __nv_bfloat16* __restrict__ oh, __nv_bfloat16* __restrict__ ol)
{
    __shared__ float s[64][33];
    const int s0 = blockIdx.x * 32;
    const int b = blockIdx.y;
    const int tid = threadIdx.x;
    const int px = tid & 31;
#pragma unroll 4
    for (int c = tid >> 5; c < 64; c += 8)
        s[c][px] = in0[(b * 64 + c) * 16384 + s0 + px];
    __syncthreads();
#pragma unroll 4
    for (int e = tid; e < 32 * 64; e += 256) {
        int p = e >> 6, c = e & 63;
        float v = s[c][p];
        __nv_bfloat16 h = __float2bfloat16(v);
        float lo = v - __bfloat162float(h);
        size_t idx = ((size_t)(b * 16384 + s0 + p)) * 64 + c;
        oh[idx] = h;
        ol[idx] = __float2bfloat16(lo);
    }
}

// ================= concat -> NHWC fp16 =================
__global__ void __launch_bounds__(256)
tc_cat_k(const float* __restrict__ x2, const float* __restrict__ up,
         __half* __restrict__ oc)
{
    __shared__ float s[128][33];
    const int s0 = blockIdx.x * 32;
    const int b = blockIdx.y;
    const int tid = threadIdx.x;
    const int px = tid & 31;
#pragma unroll 4
    for (int c = tid >> 5; c < 128; c += 8) {
        const float* src = (c < 64) ? x2 + (b * 64 + c) * HWSZ
                                    : up + (b * 64 + (c - 64)) * HWSZ;
        s[c][px] = src[s0 + px];
    }
    __syncthreads();
#pragma unroll 4
    for (int e = tid; e < 32 * 128; e += 256) {
        int p = e >> 7, c = e & 127;
        size_t idx = ((size_t)(b * HWSZ + s0 + p)) * 128 + c;
        oc[idx] = __float2half_rn(s[c][p]);
    }
}

// ================= upconv via mma (bf16x3) =================
__global__ void __launch_bounds__(256, 2)
upmma_k(const __nv_bfloat16* __restrict__ ah_g, const __nv_bfloat16* __restrict__ al_g,
        const __nv_bfloat16* __restrict__ bh_g, const __nv_bfloat16* __restrict__ bl_g,
        const float* __restrict__ upb, float* __restrict__ up)
{
    extern __shared__ char dsm[];
    constexpr int A_H = 0, A_L = 16384, B_H = 32768, B_L = 40960;
    uint32_t raw = smem_u32(dsm);
    uint32_t base = (raw + 1023u) & ~1023u;
    char* smc = dsm + (base - raw);
    const int tid = threadIdx.x;
    const int wid = tid >> 5;
    const int lane = tid & 31;

    const int p0 = blockIdx.x * 128;
    const int b  = p0 >> 14;
    const int sb = p0 & 16383;
    const int y0 = sb >> 7;
    const int oc0 = blockIdx.y * 64;

#pragma unroll
    for (int it = 0; it < 4; it++) {
        int idx = it * 256 + tid;
        int m = idx >> 3, ch = idx & 7;
        size_t gi = ((size_t)(p0 + m)) * 64 + ch * 8;
        uint32_t sw = SW128(m * 128 + ch * 16);
        cpa16(base + A_H + sw, ah_g + gi, 16);
        cpa16(base + A_L + sw, al_g + gi, 16);
    }
#pragma unroll
    for (int it = 0; it < 2; it++) {
        int idx = it * 256 + tid;
        int o = idx >> 3, ch = idx & 7;
        size_t gi = ((size_t)(oc0 + o)) * 64 + ch * 8;
        uint32_t sw = SW128(o * 128 + ch * 16);
        cpa16(base + B_H + sw, bh_g + gi, 16);
        cpa16(base + B_L + sw, bl_g + gi, 16);
    }
    cpa_commit();
    cpa_wait<0>();
    __syncthreads();

    float acc[8][4];
#pragma unroll
    for (int g = 0; g < 8; g++)
#pragma unroll
        for (int j = 0; j < 4; j++) acc[g][j] = 0.f;

    const uint32_t Ah = base + A_H, Al = base + A_L;
    const uint32_t Bh = base + B_H, Bl = base + B_L;
    const int arow = wid * 16 + (lane & 15);
    const int nrow = lane & 15;
    const int chalf = (lane >> 4) * 16;
#pragma unroll
    for (int kk = 0; kk < 4; kk++) {
        const int cb = chalf + kk * 32;
        uint32_t ah[4], al[4];
        ldm_x4(ah[0], ah[1], ah[2], ah[3], Ah + SW128(arow * 128 + cb));
        ldm_x4(al[0], al[1], al[2], al[3], Al + SW128(arow * 128 + cb));
#pragma unroll
        for (int g = 0; g < 4; g++) {
            uint32_t off = SW128((g * 16 + nrow) * 128 + cb);
            uint32_t t0, t1, t2, t3, u0, u1, u2, u3;
            ldm_x4(t0, t1, t2, t3, Bh + off);
            ldm_x4(u0, u1, u2, u3, Bl + off);
            mma_bf16(acc[2 * g],     ah, t0, t2);
            mma_bf16(acc[2 * g + 1], ah, t1, t3);
            mma_bf16(acc[2 * g],     al, t0, t2);
            mma_bf16(acc[2 * g + 1], al, t1, t3);
            mma_bf16(acc[2 * g],     ah, u0, u2);
            mma_bf16(acc[2 * g + 1], ah, u1, u3);
        }
    }
    __syncthreads();

    float* sepi = (float*)smc;
    const int em = wid * 16 + (lane >> 2);
    const int en = (lane & 3) * 2;
#pragma unroll
    for (int g = 0; g < 8; g++) {
        int n0 = g * 8 + en;
        sepi[n0 * 132 + em]           = acc[g][0];
        sepi[(n0 + 1) * 132 + em]     = acc[g][1];
        sepi[n0 * 132 + em + 8]       = acc[g][2];
        sepi[(n0 + 1) * 132 + em + 8] = acc[g][3];
    }
    __syncthreads();
#pragma unroll 4
    for (int j = 0; j < 32; j++) {
        int lin = j * 256 + tid;
        int n = lin >> 7, m = lin & 127;
        int ng = oc0 + n;
        int o = ng >> 2, k = (ng >> 1) & 1, l = ng & 1;
        float v = sepi[n * 132 + m] + upb[o];
        up[((size_t)(b * 64 + o) << 16) + (2 * y0 + k) * 256 + 2 * m + l] = v;
    }
}

// ================= ROW-STAGED offset conv (fp16 1-pass) =================
// A band (3 x 258 pixels of 64ch) staged once per 64-ch group; 9 taps index it.
// B double-buffered per tap. Weight index kc = t*CINQ + q (FIXED from R8).
__global__ void __launch_bounds__(512)
convoff_k(const __half* __restrict__ a_g, const __half* __restrict__ b_g,
          __half* __restrict__ out)
{
    extern __shared__ char dsm[];
    constexpr int NTOT = 256, NT = 128, CINQ = 2, CCH = 128;
    constexpr int A_BYTES = 776 * 128;
    constexpr int B_OFF = A_BYTES;              // 99328
    constexpr int B_BUF = NT * 128;             // 16384

    uint32_t raw = smem_u32(dsm);
    uint32_t base = (raw + 1023u) & ~1023u;
    char* smc = dsm + (base - raw);
    const int tid = threadIdx.x;
    const int wid = tid >> 5;
    const int lane = tid & 31;
    const int mw = wid & 7;
    const int nw = wid >> 3;

    const int b  = blockIdx.x >> 8;
    const int y0 = blockIdx.x & 255;
    const int sb = y0 << 8;
    const int oc0 = blockIdx.y * NT;

    auto stageA = [&](int q) {
        for (int idx = tid; idx < 6192; idx += 512) {
            int p = idx >> 3, ch = idx & 7;
            int brow = p / 258;
            int bcol = p - brow * 258;
            int gy = y0 + brow - 1;
            int gx = bcol - 1;
            bool inb = ((unsigned)gy < 256u) && ((unsigned)gx < 256u);
            size_t gi = (((size_t)b << 16) + (gy << 8) + gx) * CCH + q * 64 + ch * 8;
            if (!inb) gi = 0;
            cpa16(base + SW128(p * 128 + ch * 16), a_g + gi, inb ? 16 : 0);
        }
    };
    // kc = weight chunk index (t*CINQ + q); buf = pipeline parity
    auto stageB = [&](int kc, int buf) {
        const uint32_t bbase = base + B_OFF + buf * B_BUF;
        for (int idx = tid; idx < NT * 8; idx += 512) {
            int o = idx >> 3, ch = idx & 7;
            size_t gi = ((size_t)kc * NTOT + oc0 + o) * 64 + ch * 8;
            cpa16(bbase + SW128(o * 128 + ch * 16), b_g + gi, 16);
        }
    };

    float acc[2][8][4];
#pragma unroll
    for (int ms = 0; ms < 2; ms++)
#pragma unroll
        for (int g = 0; g < 8; g++)
#pragma unroll
            for (int j = 0; j < 4; j++) acc[ms][g][j] = 0.f;

    stageA(0);
    stageB(0 * CINQ + 0, 0);    // (q=0, t=0) -> kc=0
    cpa_commit();

    const int chalf = (lane >> 4) * 16;
    const int nrow = lane & 15;
    const int arowb = mw * 32 + (lane & 15);

#pragma unroll 1
    for (int q = 0; q < CINQ; q++) {
#pragma unroll 1
        for (int t = 0; t < 9; t++) {
            const int s = q * 9 + t;           // pipeline step (buf parity only)
            if (t < 8) {
                stageB((t + 1) * CINQ + q, (s + 1) & 1);
                cpa_commit();
                cpa_wait<1>();
            } else {
                cpa_wait<0>();
            }
            __syncthreads();

            const int ky = t / 3 - 1;
            const int kx = t % 3 - 1;
            const uint32_t Bb = base + B_OFF + (s & 1) * B_BUF;
            const int rb = (ky + 1) * 258 + kx + 1 + arowb;

#pragma unroll
            for (int kk = 0; kk < 4; kk++) {
                const int cb = chalf + kk * 32;
                uint32_t ah[2][4];
#pragma unroll
                for (int ms = 0; ms < 2; ms++) {
                    int r = rb + ms * 16;
                    ldm_x4(ah[ms][0], ah[ms][1], ah[ms][2], ah[ms][3],
                           base + SW128(r * 128 + cb));
                }
#pragma unroll
                for (int g = 0; g < 4; g++) {
                    uint32_t off = SW128((nw * 64 + g * 16 + nrow) * 128 + cb);
                    uint32_t t0, t1, t2, t3;
                    ldm_x4(t0, t1, t2, t3, Bb + off);
#pragma unroll
                    for (int ms = 0; ms < 2; ms++) {
                        mma_f16(acc[ms][2 * g],     ah[ms], t0, t2);
                        mma_f16(acc[ms][2 * g + 1], ah[ms], t1, t3);
                    }
                }
            }
            __syncthreads();

            if (t == 8 && q + 1 < CINQ) {
                stageA(q + 1);
                stageB(0 * CINQ + (q + 1), (s + 1) & 1);   // (q+1, t=0) -> kc=q+1
                cpa_commit();
            }
        }
    }

    // ---- epilogue: [n=128][m=256] fp32 in smem, fp16 NCHW writes ----
    float* sepi = (float*)smc;
    const int em = mw * 32 + (lane >> 2);
    const int ecol = (lane & 3) * 2;
#pragma unroll
    for (int ms = 0; ms < 2; ms++) {
        int m = em + ms * 16;
#pragma unroll
        for (int g = 0; g < 4; g++) {
            int nb = nw * 64 + g * 16 + ecol;
            sepi[nb * 260 + m]           = acc[ms][2 * g][0];
            sepi[(nb + 1) * 260 + m]     = acc[ms][2 * g][1];
            sepi[nb * 260 + m + 8]       = acc[ms][2 * g][2];
            sepi[(nb + 1) * 260 + m + 8] = acc[ms][2 * g][3];
            int nb2 = nb + 8;
            sepi[nb2 * 260 + m]           = acc[ms][2 * g + 1][0];
            sepi[(nb2 + 1) * 260 + m]     = acc[ms][2 * g + 1][1];
            sepi[nb2 * 260 + m + 8]       = acc[ms][2 * g + 1][2];
            sepi[(nb2 + 1) * 260 + m + 8] = acc[ms][2 * g + 1][3];
        }
    }
    __syncthreads();

#pragma unroll
    for (int j = 0; j < 16; j++) {
        int lin = j * 512 + tid;
        int n = lin >> 6;
        int seg = lin & 63;
        const float* sp = sepi + n * 260 + seg * 4;
        __half h0 = __float2half_rn(sp[0]);
        __half h1 = __float2half_rn(sp[1]);
        __half h2 = __float2half_rn(sp[2]);
        __half h3 = __float2half_rn(sp[3]);
        unsigned short hs[4] = {*(unsigned short*)&h0, *(unsigned short*)&h1,
                                *(unsigned short*)&h2, *(unsigned short*)&h3};
        *(uint2*)((unsigned short*)out + (((size_t)(b * NTOT + oc0 + n)) << 16)
                  + sb + seg * 4) = *(uint2*)hs;
    }
}

// ================= fp16 implicit-GEMM conv1/conv2 =================
template<int NTOT, int CINQ, int NT, int EPI, int TWOPASS>
__global__ void __launch_bounds__(512)
convmma_k(const __half* __restrict__ a_g,
          const __half* __restrict__ bh_g, const __half* __restrict__ bl_g,
          const float* __restrict__ bias, float* __restrict__ out, float* __restrict__ red)
{
    extern __shared__ char dsm[];
    constexpr int CCH = CINQ * 64;
    constexpr int NC  = CINQ * 9;
    constexpr int NW  = NT / 2;
    constexpr int NG  = NW / 16;
    constexpr int B_OFF = 32768;
    constexpr int STAGE = 32768 + NT * 128 * (1 + TWOPASS);

    uint32_t raw = smem_u32(dsm);
    uint32_t base = (raw + 1023u) & ~1023u;
    char* smc = dsm + (base - raw);
    const int tid = threadIdx.x;
    const int wid = tid >> 5;
    const int lane = tid & 31;
    const int mw = wid & 7;
    const int nw = wid >> 3;

    const int b  = blockIdx.x >> 8;
    const int y0 = blockIdx.x & 255;
    const int sb = y0 << 8;
    const int oc0 = blockIdx.y * NT;

    auto stage = [&](int chunk, int buf) {
        const int t = chunk / CINQ;
        const int q = chunk - t * CINQ;
        const int ky = t / 3 - 1;
        const int kx = t % 3 - 1;
        const uint32_t sbase = base + buf * STAGE;
        const int yy = y0 + ky;
        const bool yin = (unsigned)yy < 256u;
#pragma unroll
        for (int it = 0; it < 4; it++) {
            int idx = it * 512 + tid;
            int m = idx >> 3, ch = idx & 7;
            int xx = m + kx;
            bool inb = yin && ((unsigned)xx < 256u);
            size_t gi = (((size_t)b << 16) + (yy << 8) + xx) * CCH + q * 64 + ch * 8;
            if (!inb) gi = 0;
            cpa16(sbase + SW128(m * 128 + ch * 16), a_g + gi, inb ? 16 : 0);
        }
        for (int idx = tid; idx < NT * 8; idx += 512) {
            int o = idx >> 3, ch = idx & 7;
            size_t gi = ((size_t)chunk * NTOT + oc0 + o) * 64 + ch * 8;
            uint32_t sw = SW128(o * 128 + ch * 16);
            cpa16(sbase + B_OFF + sw, bh_g + gi, 16);
            if (TWOPASS) cpa16(sbase + B_OFF + NT * 128 + sw, bl_g + gi, 16);
        }
        cpa_commit();
    };

    float acc[2][NW / 8][4];
#pragma unroll
    for (int ms = 0; ms < 2; ms++)
#pragma unroll
        for (int g = 0; g < NW / 8; g++)
#pragma unroll
            for (int j = 0; j < 4; j++) acc[ms][g][j] = 0.f;

    stage(0, 0);

    const int chalf = (lane >> 4) * 16;
    const int nrow = lane & 15;
    const int arowb = mw * 32 + (lane & 15);

#pragma unroll 1
    for (int chunk = 0; chunk < NC; chunk++) {
        if (chunk + 1 < NC) {
            stage(chunk + 1, (chunk + 1) & 1);
            cpa_wait<1>();
        } else {
            cpa_wait<0>();
        }
        __syncthreads();

        const uint32_t sbase = base + (chunk & 1) * STAGE;
        const uint32_t Ab = sbase;
        const uint32_t Bh = sbase + B_OFF, Bl = sbase + B_OFF + NT * 128;

#pragma unroll
        for (int kk = 0; kk < 4; kk++) {
            const int cb = chalf + kk * 32;
            uint32_t ah[2][4];
#pragma unroll
            for (int ms = 0; ms < 2; ms++) {
                int r = arowb + ms * 16;
                ldm_x4(ah[ms][0], ah[ms][1], ah[ms][2], ah[ms][3], Ab + SW128(r * 128 + cb));
            }
#pragma unroll
            for (int g = 0; g < NG; g++) {
                uint32_t off = SW128((nw * NW + g * 16 + nrow) * 128 + cb);
                uint32_t t0, t1, t2, t3;
                ldm_x4(t0, t1, t2, t3, Bh + off);
#pragma unroll
                for (int ms = 0; ms < 2; ms++) {
                    mma_f16(acc[ms][2 * g],     ah[ms], t0, t2);
                    mma_f16(acc[ms][2 * g + 1], ah[ms], t1, t3);
                }
                if (TWOPASS) {
                    uint32_t u0, u1, u2, u3;
                    ldm_x4(u0, u1, u2, u3, Bl + off);
#pragma unroll
                    for (int ms = 0; ms < 2; ms++) {
                        mma_f16(acc[ms][2 * g],     ah[ms], u0, u2);
                        mma_f16(acc[ms][2 * g + 1], ah[ms], u1, u3);
                    }
                }
            }
        }
        __syncthreads();
    }

    float* sepi = (float*)smc;
    const int em = mw * 32 + (lane >> 2);
    const int ecol = (lane & 3) * 2;
#pragma unroll
    for (int ms = 0; ms < 2; ms++) {
        int m = em + ms * 16;
#pragma unroll
        for (int g = 0; g < NG; g++) {
            int nb = nw * NW + g * 16 + ecol;
            sepi[nb * 260 + m]           = acc[ms][2 * g][0];
            sepi[(nb + 1) * 260 + m]     = acc[ms][2 * g][1];
            sepi[nb * 260 + m + 8]       = acc[ms][2 * g][2];
            sepi[(nb + 1) * 260 + m + 8] = acc[ms][2 * g][3];
            int nb2 = nb + 8;
            sepi[nb2 * 260 + m]           = acc[ms][2 * g + 1][0];
            sepi[(nb2 + 1) * 260 + m]     = acc[ms][2 * g + 1][1];
            sepi[nb2 * 260 + m + 8]       = acc[ms][2 * g + 1][2];
            sepi[(nb2 + 1) * 260 + m + 8] = acc[ms][2 * g + 1][3];
        }
    }
    __syncthreads();

    if (EPI == 0) {
#pragma unroll
        for (int j = 0; j < NT / 8; j++) {
            int lin = j * 512 + tid;
            int n = lin >> 6;
            int seg = lin & 63;
            float4 v = *(float4*)(sepi + n * 260 + seg * 4);
            float bz = bias ? bias[oc0 + n] : 0.f;
            v.x += bz; v.y += bz; v.z += bz; v.w += bz;
            *(float4*)(out + (((size_t)(b * NTOT + oc0 + n)) << 16) + sb + seg * 4) = v;
        }
    } else {
#pragma unroll
        for (int j = 0; j < 8; j++) {
            int lin = j * 512 + tid;
            int m = lin >> 4;
            int cq = lin & 15;
            float4 v;
            v.x = sepi[(cq * 4 + 0) * 260 + m] + bias[cq * 4 + 0];
            v.y = sepi[(cq * 4 + 1) * 260 + m] + bias[cq * 4 + 1];
            v.z = sepi[(cq * 4 + 2) * 260 + m] + bias[cq * 4 + 2];
            v.w = sepi[(cq * 4 + 3) * 260 + m] + bias[cq * 4 + 3];
            *(float4*)(out + ((size_t)(b * 65536 + sb + m)) * 64 + cq * 4) = v;
        }
    }

    if (red) {
        float* sred = sepi + NT * 260;
        int n = tid >> 3, part = tid & 7;
        float bz = bias ? bias[oc0 + n] : 0.f;
        float s1 = 0.f, s2 = 0.f;
        const float* rowp = sepi + n * 260 + part * 32;
#pragma unroll
        for (int j = 0; j < 32; j++) {
            float v = rowp[j] + bz;
            s1 += v;
            s2 = fmaf(v, v, s2);
        }
        sred[(0 * 64 + n) * 8 + part] = s1;
        sred[(1 * 64 + n) * 8 + part] = s2;
        __syncthreads();
        if (tid < 128) {
            int which = tid >> 6, n2 = tid & 63;
            const float* pr = sred + (which * 64 + n2) * 8;
            float s = 0.f;
#pragma unroll
            for (int j = 0; j < 8; j++) s += pr[j];
            atomicAdd(red + which * 64 + oc0 + n2, s);
        }
    }
}

// ================= deformable gather (fp16 offsets) -> xd NHWC fp16 =================
__global__ void __launch_bounds__(256)
gathercvt_k(const float* __restrict__ x2, const float* __restrict__ up,
            const __half* __restrict__ offs, __half* __restrict__ oc)
{
    __shared__ float s[128][33];
    const int s0 = blockIdx.x * 32;
    const int b = blockIdx.y;
    const int tid = threadIdx.x;
    const int px = tid & 31;
    const int hw = s0 + px;
    const int h = hw >> 8;
    const int w = hw & 255;
#pragma unroll 4
    for (int c = tid >> 5; c < 128; c += 8) {
        const float* src = (c < 64) ? x2 + (b * 64 + c) * HWSZ
                                    : up + (b * 64 + (c - 64)) * HWSZ;
        int obase = b * C256 * HWSZ + c * 2 * HWSZ + h * (2 * WW) + 2 * w;
        float oy = __half2float(offs[obase]);
        float ox = __half2float(offs[obase + 1]);
        float cy = fminf(fmaxf(oy + (float)h, 0.f), 255.f);
        float cx = fminf(fmaxf(ox + (float)w, 0.f), 255.f);
        float y0f = floorf(cy), x0f = floorf(cx);
        int y0 = (int)y0f;
        int x0 = (int)x0f;
        int y1 = (int)ceilf(cy);
        int x1 = (int)ceilf(cx);
        float v00 = src[y0 * WW + x0];
        float v10 = src[y1 * WW + x0];
        float v01 = src[y0 * WW + x1];
        float v11 = src[y1 * WW + x1];
        float wy = cy - y0f, wx = cx - x0f;
        float vt = v00 + (v10 - v00) * wy;
        float vb = v01 + (v11 - v01) * wy;
        s[c][px] = vt + (vb - vt) * wx;
    }
    __syncthreads();
#pragma unroll 4
    for (int e = tid; e < 32 * 128; e += 256) {
        int p = e >> 7, c = e & 127;
        size_t idx = ((size_t)(b * HWSZ + s0 + p)) * 128 + c;
        oc[idx] = __float2half_rn(s[c][p]);
    }
}

// ================= small kernels =================
__global__ void zero_red_k() { g_red[threadIdx.x] = 0.f; }

__global__ void bnfin_k(const float* __restrict__ red,
                        const float* __restrict__ gamma, const float* __restrict__ beta,
                        float* __restrict__ ab)
{
    int c = threadIdx.x;
    const float invn = 1.f / 131072.f;
    float m = red[c] * invn;
    float var = fmaf(-m, m, red[64 + c] * invn);
    float a = gamma[c] * rsqrtf(var + 1e-5f);
    ab[c] = a;
    ab[64 + c] = fmaf(-m, a, beta[c]);
}

__global__ void __launch_bounds__(256)
afsplit_k(const float* __restrict__ in, const float* __restrict__ ab,
          __half* __restrict__ oc)
{
    int i4 = blockIdx.x * 256 + threadIdx.x;
    int c0 = (i4 & 15) * 4;
    float4 v = *(const float4*)(in + (size_t)i4 * 4);
    float vv[4] = {v.x, v.y, v.z, v.w};
    unsigned short hs[4];
#pragma unroll
    for (int j = 0; j < 4; j++) {
        int c = c0 + j;
        float y = fmaxf(fmaf(vv[j], __ldg(ab + c), __ldg(ab + 64 + c)), 0.f);
        __half hb = __float2half_rn(y);
        hs[j] = *(unsigned short*)&hb;
    }
    *(uint2*)((unsigned short*)oc + (size_t)i4 * 4) = *(uint2*)hs;
}

__global__ void __launch_bounds__(256)
bnrelu_out_k(const float* __restrict__ buf, const float* __restrict__ ab,
             float* __restrict__ out)
{
    int i4 = blockIdx.x * 256 + threadIdx.x;
    int c = (i4 >> 14) & 63;
    float a = __ldg(ab + c), bz = __ldg(ab + 64 + c);
    float4 v = *(const float4*)(buf + (size_t)i4 * 4);
    v.x = fmaxf(fmaf(v.x, a, bz), 0.f);
    v.y = fmaxf(fmaf(v.y, a, bz), 0.f);
    v.z = fmaxf(fmaf(v.z, a, bz), 0.f);
    v.w = fmaxf(fmaf(v.w, a, bz), 0.f);
    *(float4*)(out + (size_t)i4 * 4) = v;
}

// ================= launch =================
extern "C" void kernel_launch(void* const* d_in, const int* in_sizes, int n_in,
                              void* d_out, int out_size)
{
    const float* x1   = (const float*)d_in[0];
    const float* x2   = (const float*)d_in[1];
    const float* up_w = (const float*)d_in[2];
    const float* up_b = (const float*)d_in[3];
    const float* offw = (const float*)d_in[4];
    const float* c1w  = (const float*)d_in[5];
    const float* c1b  = (const float*)d_in[6];
    const float* g1   = (const float*)d_in[7];
    const float* b1   = (const float*)d_in[8];
    const float* c2w  = (const float*)d_in[9];
    const float* c2b  = (const float*)d_in[10];
    const float* g2   = (const float*)d_in[11];
    const float* b2   = (const float*)d_in[12];
    float* outp = (float*)d_out;

    float *p_up, *p_h1raw, *p_b2, *p_red, *p_ab1, *p_ab2;
    cudaGetSymbolAddress((void**)&p_up,    g_up);
    cudaGetSymbolAddress((void**)&p_h1raw, g_h1raw);
    cudaGetSymbolAddress((void**)&p_b2,    g_b2);
    cudaGetSymbolAddress((void**)&p_red,   g_red);
    cudaGetSymbolAddress((void**)&p_ab1,   g_ab1);
    cudaGetSymbolAddress((void**)&p_ab2,   g_ab2);
    __nv_bfloat16 *p_x1_h, *p_x1_l, *p_wu_h, *p_wu_l;
    cudaGetSymbolAddress((void**)&p_x1_h, g_x1_h);
    cudaGetSymbolAddress((void**)&p_x1_l, g_x1_l);
    cudaGetSymbolAddress((void**)&p_wu_h, g_wu_h);
    cudaGetSymbolAddress((void**)&p_wu_l, g_wu_l);
    __half *p_off, *p_cat, *p_xd, *p_h1, *p_wo, *p_w1h, *p_w1l, *p_w2h, *p_w2l;
    cudaGetSymbolAddress((void**)&p_off, g_off);
    cudaGetSymbolAddress((void**)&p_cat, g_cat);
    cudaGetSymbolAddress((void**)&p_xd,  g_xd);
    cudaGetSymbolAddress((void**)&p_h1,  g_h1);
    cudaGetSymbolAddress((void**)&p_wo,  g_wo);
    cudaGetSymbolAddress((void**)&p_w1h, g_w1h);
    cudaGetSymbolAddress((void**)&p_w1l, g_w1l);
    cudaGetSymbolAddress((void**)&p_w2h, g_w2h);
    cudaGetSymbolAddress((void**)&p_w2l, g_w2l);

    const int smem_offc = 133120 + 2048;   // 135168
    const int smem_c    = 98304 + 2048;
    const int smem_up   = 49152 + 1024;
    cudaFuncSetAttribute(convoff_k, cudaFuncAttributeMaxDynamicSharedMemorySize, smem_offc);
    cudaFuncSetAttribute(convmma_k<64, 2, 64, 1, 1>, cudaFuncAttributeMaxDynamicSharedMemorySize, smem_c);
    cudaFuncSetAttribute(convmma_k<64, 1, 64, 0, 1>, cudaFuncAttributeMaxDynamicSharedMemorySize, smem_c);
    cudaFuncSetAttribute(upmma_k, cudaFuncAttributeMaxDynamicSharedMemorySize, smem_up);

    // 0) zero stats + weight prep
    zero_red_k<<<1, 256>>>();
    wprep_f16_k<<<(256 * 128 * 9 + 255) / 256, 256>>>(offw, p_wo, 256, 128);
    wprep_f16x2_k<<<(64 * 128 * 9 + 255) / 256, 256>>>(c1w, p_w1h, p_w1l, 64, 128);
    wprep_f16x2_k<<<(64 * 64 * 9 + 255) / 256, 256>>>(c2w, p_w2h, p_w2l, 64, 64);
    upwprep_k<<<64, 256>>>(up_w, p_wu_h, p_wu_l);

    // 1) x1 -> NHWC bf16 hi/lo, upconv via bf16x3 mma
    tc_x1_k<<<dim3(512, 2), 256>>>(x1, p_x1_h, p_x1_l);
    upmma_k<<<dim3(256, 4), 256, smem_up>>>(p_x1_h, p_x1_l, p_wu_h, p_wu_l, up_b, p_up);

    // 2) concat -> NHWC fp16
    tc_cat_k<<<dim3(2048, 2), 256>>>(x2, p_up, p_cat);

    // 3) row-staged offset conv -> g_off fp16 NCHW
    convoff_k<<<dim3(512, 2), 512, smem_offc>>>(p_cat, p_wo, p_off);

    // 4) gather (fp16 offsets) -> xd NHWC fp16
    gathercvt_k<<<dim3(2048, 2), 256>>>(x2, p_up, p_off, p_xd);

    // 5) conv1 (fp16 2-pass) -> NHWC fp32 + BN1 stats
    convmma_k<64, 2, 64, 1, 1><<<dim3(512, 1), 512, smem_c>>>(
        p_xd, p_w1h, p_w1l, c1b, p_h1raw, p_red);
    bnfin_k<<<1, 64>>>(p_red, g1, b1, p_ab1);

    // 6) BN1 affine + relu -> fp16
    afsplit_k<<<8192, 256>>>(p_h1raw, p_ab1, p_h1);

    // 7) conv2 (fp16 2-pass) -> NCHW fp32 + BN2 stats
    convmma_k<64, 1, 64, 0, 1><<<dim3(512, 1), 512, smem_c>>>(
        p_h1, p_w2h, p_w2l, c2b, p_b2, p_red + 128);
    bnfin_k<<<1, 64>>>(p_red + 128, g2, b2, p_ab2);

    // 8) final BN+ReLU
    bnrelu_out_k<<<8192, 256>>>(p_b2, p_ab2, outp);
}

// round 10
// speedup vs baseline: 2.0132x; 1.0103x over previous
#include <cuda_runtime.h>
#include <cuda_bf16.h>
#include <cuda_fp16.h>
#include <math.h>
#include <stdint.h>

#define HH 256
#define WW 256
#define HWSZ 65536
#define BB 2
#define C64 64
#define C128 128
#define C256 256

#define SW128(off) ((off) ^ (((off) >> 3) & 0x70))

__device__ __forceinline__ uint32_t smem_u32(const void* p) {
    uint32_t a;
    asm("{ .reg .u64 t; cvta.to.shared.u64 t, %1; cvt.u32.u64 %0, t; }" : "=r"(a) : "l"(p));
    return a;
}
__device__ __forceinline__ void cpa16(uint32_t dst, const void* src, int sz) {
    asm volatile("cp.async.cg.shared.global [%0], [%1], 16, %2;"
                 :: "r"(dst), "l"(src), "r"(sz) : "memory");
}
__device__ __forceinline__ void cpa_commit() {
    asm volatile("cp.async.commit_group;" ::: "memory");
}
template<int N>
__device__ __forceinline__ void cpa_wait() {
    asm volatile("cp.async.wait_group %0;" :: "n"(N) : "memory");
}
__device__ __forceinline__ void ldm_x4(uint32_t& r0, uint32_t& r1, uint32_t& r2, uint32_t& r3,
                                       uint32_t addr) {
    asm volatile("ldmatrix.sync.aligned.m8n8.x4.shared.b16 {%0,%1,%2,%3}, [%4];"
                 : "=r"(r0), "=r"(r1), "=r"(r2), "=r"(r3) : "r"(addr));
}
__device__ __forceinline__ void mma_bf16(float* c, const uint32_t* a, uint32_t b0, uint32_t b1) {
    asm volatile("mma.sync.aligned.m16n8k16.row.col.f32.bf16.bf16.f32 "
                 "{%0,%1,%2,%3}, {%4,%5,%6,%7}, {%8,%9}, {%0,%1,%2,%3};"
                 : "+f"(c[0]), "+f"(c[1]), "+f"(c[2]), "+f"(c[3])
                 : "r"(a[0]), "r"(a[1]), "r"(a[2]), "r"(a[3]), "r"(b0), "r"(b1));
}
__device__ __forceinline__ void mma_f16(float* c, const uint32_t* a, uint32_t b0, uint32_t b1) {
    asm volatile("mma.sync.aligned.m16n8k16.row.col.f32.f16.f16.f32 "
                 "{%0,%1,%2,%3}, {%4,%5,%6,%7}, {%8,%9}, {%0,%1,%2,%3};"
                 : "+f"(c[0]), "+f"(c[1]), "+f"(c[2]), "+f"(c[3])
                 : "r"(a[0]), "r"(a[1]), "r"(a[2]), "r"(a[3]), "r"(b0), "r"(b1));
}

// ================= scratch (device globals) =================
__device__ float g_up   [BB * C64 * HWSZ];
__device__ __half g_off [BB * C256 * HWSZ];
__device__ float g_h1raw[BB * HWSZ * C64];
__device__ float g_b2   [BB * C64 * HWSZ];
__device__ float g_red[256];
__device__ float g_ab1[128];
__device__ float g_ab2[128];
__device__ __nv_bfloat16 g_x1_h[BB * 16384 * C64];
__device__ __nv_bfloat16 g_x1_l[BB * 16384 * C64];
__device__ __nv_bfloat16 g_wu_h[C256 * 64];
__device__ __nv_bfloat16 g_wu_l[C256 * 64];
__device__ __half g_cat [BB * HWSZ * C128];
__device__ __half g_xd  [BB * HWSZ * C128];
__device__ __half g_h1  [BB * HWSZ * C64];
__device__ __half g_wo  [18 * C256 * 64];
__device__ __half g_w1h [18 * C64 * 64];
__device__ __half g_w1l [18 * C64 * 64];
__device__ __half g_w2h [9 * C64 * 64];
__device__ __half g_w2l [9 * C64 * 64];

// ================= weight prep =================
__global__ void wprep_f16_k(const float* __restrict__ w, __half* __restrict__ wh,
                            int N, int CIN)
{
    int i = blockIdx.x * blockDim.x + threadIdx.x;
    if (i >= N * CIN * 9) return;
    int t  = i % 9;
    int ci = (i / 9) % CIN;
    int o  = i / (9 * CIN);
    int q = ci >> 6, cc = ci & 63;
    int kc = t * (CIN >> 6) + q;
    wh[(kc * N + o) * 64 + cc] = __float2half_rn(w[i]);
}
__global__ void wprep_f16x2_k(const float* __restrict__ w, __half* __restrict__ wh,
                              __half* __restrict__ wl, int N, int CIN)
{
    int i = blockIdx.x * blockDim.x + threadIdx.x;
    if (i >= N * CIN * 9) return;
    int t  = i % 9;
    int ci = (i / 9) % CIN;
    int o  = i / (9 * CIN);
    int q = ci >> 6, cc = ci & 63;
    int kc = t * (CIN >> 6) + q;
    float v = w[i];
    __half h = __float2half_rn(v);
    float lo = v - __half2float(h);
    int dst = (kc * N + o) * 64 + cc;
    wh[dst] = h;
    wl[dst] = __float2half_rn(lo);
}
__global__ void upwprep_k(const float* __restrict__ w, __nv_bfloat16* __restrict__ wh,
                          __nv_bfloat16* __restrict__ wl)
{
    int s = blockIdx.x * blockDim.x + threadIdx.x;
    if (s >= 64 * 256) return;
    int n = s & 255;
    int cc = s >> 8;
    float v = w[s];
    __nv_bfloat16 h = __float2bfloat16(v);
    float lo = v - __bfloat162float(h);
    wh[n * 64 + cc] = h;
    wl[n * 64 + cc] = __float2bfloat16(lo);
}

// ================= x1 NCHW -> NHWC bf16 hi/lo =================
__global__ void __launch_bounds__(256)
tc_x1_k(const float* __restrict__ in0,
        __nv_bfloat16* __restrict__ oh, __nv_bfloat16* __restrict__ ol)
{
    __shared__ float s[64][33];
    const int s0 = blockIdx.x * 32;
    const int b = blockIdx.y;
    const int tid = threadIdx.x;
    const int px = tid & 31;
#pragma unroll 4
    for (int c = tid >> 5; c < 64; c += 8)
        s[c][px] = in0[(b * 64 + c) * 16384 + s0 + px];
    __syncthreads();
#pragma unroll 4
    for (int e = tid; e < 32 * 64; e += 256) {
        int p = e >> 6, c = e & 63;
        float v = s[c][p];
        __nv_bfloat16 h = __float2bfloat16(v);
        float lo = v - __bfloat162float(h);
        size_t idx = ((size_t)(b * 16384 + s0 + p)) * 64 + c;
        oh[idx] = h;
        ol[idx] = __float2bfloat16(lo);
    }
}

// ================= concat -> NHWC fp16 =================
__global__ void __launch_bounds__(256)
tc_cat_k(const float* __restrict__ x2, const float* __restrict__ up,
         __half* __restrict__ oc)
{
    __shared__ float s[128][33];
    const int s0 = blockIdx.x * 32;
    const int b = blockIdx.y;
    const int tid = threadIdx.x;
    const int px = tid & 31;
#pragma unroll 4
    for (int c = tid >> 5; c < 128; c += 8) {
        const float* src = (c < 64) ? x2 + (b * 64 + c) * HWSZ
                                    : up + (b * 64 + (c - 64)) * HWSZ;
        s[c][px] = src[s0 + px];
    }
    __syncthreads();
#pragma unroll 4
    for (int e = tid; e < 32 * 128; e += 256) {
        int p = e >> 7, c = e & 127;
        size_t idx = ((size_t)(b * HWSZ + s0 + p)) * 128 + c;
        oc[idx] = __float2half_rn(s[c][p]);
    }
}

// ================= upconv via mma (bf16x3) =================
__global__ void __launch_bounds__(256, 2)
upmma_k(const __nv_bfloat16* __restrict__ ah_g, const __nv_bfloat16* __restrict__ al_g,
        const __nv_bfloat16* __restrict__ bh_g, const __nv_bfloat16* __restrict__ bl_g,
        const float* __restrict__ upb, float* __restrict__ up)
{
    extern __shared__ char dsm[];
    constexpr int A_H = 0, A_L = 16384, B_H = 32768, B_L = 40960;
    uint32_t raw = smem_u32(dsm);
    uint32_t base = (raw + 1023u) & ~1023u;
    char* smc = dsm + (base - raw);
    const int tid = threadIdx.x;
    const int wid = tid >> 5;
    const int lane = tid & 31;

    const int p0 = blockIdx.x * 128;
    const int b  = p0 >> 14;
    const int sb = p0 & 16383;
    const int y0 = sb >> 7;
    const int oc0 = blockIdx.y * 64;

#pragma unroll
    for (int it = 0; it < 4; it++) {
        int idx = it * 256 + tid;
        int m = idx >> 3, ch = idx & 7;
        size_t gi = ((size_t)(p0 + m)) * 64 + ch * 8;
        uint32_t sw = SW128(m * 128 + ch * 16);
        cpa16(base + A_H + sw, ah_g + gi, 16);
        cpa16(base + A_L + sw, al_g + gi, 16);
    }
#pragma unroll
    for (int it = 0; it < 2; it++) {
        int idx = it * 256 + tid;
        int o = idx >> 3, ch = idx & 7;
        size_t gi = ((size_t)(oc0 + o)) * 64 + ch * 8;
        uint32_t sw = SW128(o * 128 + ch * 16);
        cpa16(base + B_H + sw, bh_g + gi, 16);
        cpa16(base + B_L + sw, bl_g + gi, 16);
    }
    cpa_commit();
    cpa_wait<0>();
    __syncthreads();

    float acc[8][4];
#pragma unroll
    for (int g = 0; g < 8; g++)
#pragma unroll
        for (int j = 0; j < 4; j++) acc[g][j] = 0.f;

    const uint32_t Ah = base + A_H, Al = base + A_L;
    const uint32_t Bh = base + B_H, Bl = base + B_L;
    const int arow = wid * 16 + (lane & 15);
    const int nrow = lane & 15;
    const int chalf = (lane >> 4) * 16;
#pragma unroll
    for (int kk = 0; kk < 4; kk++) {
        const int cb = chalf + kk * 32;
        uint32_t ah[4], al[4];
        ldm_x4(ah[0], ah[1], ah[2], ah[3], Ah + SW128(arow * 128 + cb));
        ldm_x4(al[0], al[1], al[2], al[3], Al + SW128(arow * 128 + cb));
#pragma unroll
        for (int g = 0; g < 4; g++) {
            uint32_t off = SW128((g * 16 + nrow) * 128 + cb);
            uint32_t t0, t1, t2, t3, u0, u1, u2, u3;
            ldm_x4(t0, t1, t2, t3, Bh + off);
            ldm_x4(u0, u1, u2, u3, Bl + off);
            mma_bf16(acc[2 * g],     ah, t0, t2);
            mma_bf16(acc[2 * g + 1], ah, t1, t3);
            mma_bf16(acc[2 * g],     al, t0, t2);
            mma_bf16(acc[2 * g + 1], al, t1, t3);
            mma_bf16(acc[2 * g],     ah, u0, u2);
            mma_bf16(acc[2 * g + 1], ah, u1, u3);
        }
    }
    __syncthreads();

    float* sepi = (float*)smc;
    const int em = wid * 16 + (lane >> 2);
    const int en = (lane & 3) * 2;
#pragma unroll
    for (int g = 0; g < 8; g++) {
        int n0 = g * 8 + en;
        sepi[n0 * 132 + em]           = acc[g][0];
        sepi[(n0 + 1) * 132 + em]     = acc[g][1];
        sepi[n0 * 132 + em + 8]       = acc[g][2];
        sepi[(n0 + 1) * 132 + em + 8] = acc[g][3];
    }
    __syncthreads();
#pragma unroll 4
    for (int j = 0; j < 32; j++) {
        int lin = j * 256 + tid;
        int n = lin >> 7, m = lin & 127;
        int ng = oc0 + n;
        int o = ng >> 2, k = (ng >> 1) & 1, l = ng & 1;
        float v = sepi[n * 132 + m] + upb[o];
        up[((size_t)(b * 64 + o) << 16) + (2 * y0 + k) * 256 + 2 * m + l] = v;
    }
}

// ============ ROW-STAGED implicit-GEMM 3x3 conv (generalized) ============
// A band (3 x 258 px of 64ch) staged once per 64-ch group; 9 taps by row shift.
// B (hi[/lo]) double-buffered per tap. Weight index kc = t*CINQ + q.
// EPI 0: NCHW fp32 + bias + stats. EPI 1: NHWC fp32 + bias + stats.
// EPI 2: NCHW fp16 (no bias/stats).
template<int NTOT, int CINQ, int NT, int EPI, int TWOPASS>
__global__ void __launch_bounds__(512)
convrs_k(const __half* __restrict__ a_g,
         const __half* __restrict__ bh_g, const __half* __restrict__ bl_g,
         const float* __restrict__ bias, void* __restrict__ outv,
         float* __restrict__ red)
{
    extern __shared__ char dsm[];
    constexpr int CCH = CINQ * 64;
    constexpr int NW  = NT / 2;
    constexpr int NG  = NW / 16;
    constexpr int A_BYTES = 776 * 128;          // 774 rows used
    constexpr int B_OFF = A_BYTES;              // 99328
    constexpr int B_BUF = NT * 128 * (1 + TWOPASS);

    uint32_t raw = smem_u32(dsm);
    uint32_t base = (raw + 1023u) & ~1023u;
    char* smc = dsm + (base - raw);
    const int tid = threadIdx.x;
    const int wid = tid >> 5;
    const int lane = tid & 31;
    const int mw = wid & 7;
    const int nw = wid >> 3;

    const int b  = blockIdx.x >> 8;
    const int y0 = blockIdx.x & 255;
    const int sb = y0 << 8;
    const int oc0 = blockIdx.y * NT;

    auto stageA = [&](int q) {
        for (int idx = tid; idx < 6192; idx += 512) {
            int p = idx >> 3, ch = idx & 7;
            int brow = p / 258;
            int bcol = p - brow * 258;
            int gy = y0 + brow - 1;
            int gx = bcol - 1;
            bool inb = ((unsigned)gy < 256u) && ((unsigned)gx < 256u);
            size_t gi = (((size_t)b << 16) + (gy << 8) + gx) * CCH + q * 64 + ch * 8;
            if (!inb) gi = 0;
            cpa16(base + SW128(p * 128 + ch * 16), a_g + gi, inb ? 16 : 0);
        }
    };
    auto stageB = [&](int kc, int buf) {
        const uint32_t bbase = base + B_OFF + buf * B_BUF;
        for (int idx = tid; idx < NT * 8; idx += 512) {
            int o = idx >> 3, ch = idx & 7;
            size_t gi = ((size_t)kc * NTOT + oc0 + o) * 64 + ch * 8;
            uint32_t sw = SW128(o * 128 + ch * 16);
            cpa16(bbase + sw, bh_g + gi, 16);
            if (TWOPASS) cpa16(bbase + NT * 128 + sw, bl_g + gi, 16);
        }
    };

    float acc[2][NW / 8][4];
#pragma unroll
    for (int ms = 0; ms < 2; ms++)
#pragma unroll
        for (int g = 0; g < NW / 8; g++)
#pragma unroll
            for (int j = 0; j < 4; j++) acc[ms][g][j] = 0.f;

    stageA(0);
    stageB(0, 0);
    cpa_commit();

    const int chalf = (lane >> 4) * 16;
    const int nrow = lane & 15;
    const int arowb = mw * 32 + (lane & 15);

#pragma unroll 1
    for (int q = 0; q < CINQ; q++) {
#pragma unroll 1
        for (int t = 0; t < 9; t++) {
            const int s = q * 9 + t;
            if (t < 8) {
                stageB((t + 1) * CINQ + q, (s + 1) & 1);
                cpa_commit();
                cpa_wait<1>();
            } else {
                cpa_wait<0>();
            }
            __syncthreads();

            const int ky = t / 3 - 1;
            const int kx = t % 3 - 1;
            const uint32_t Bb = base + B_OFF + (s & 1) * B_BUF;
            const uint32_t Bl = Bb + NT * 128;
            const int rb = (ky + 1) * 258 + kx + 1 + arowb;

#pragma unroll
            for (int kk = 0; kk < 4; kk++) {
                const int cb = chalf + kk * 32;
                uint32_t ah[2][4];
#pragma unroll
                for (int ms = 0; ms < 2; ms++) {
                    int r = rb + ms * 16;
                    ldm_x4(ah[ms][0], ah[ms][1], ah[ms][2], ah[ms][3],
                           base + SW128(r * 128 + cb));
                }
#pragma unroll
                for (int g = 0; g < NG; g++) {
                    uint32_t off = SW128((nw * NW + g * 16 + nrow) * 128 + cb);
                    uint32_t t0, t1, t2, t3;
                    ldm_x4(t0, t1, t2, t3, Bb + off);
#pragma unroll
                    for (int ms = 0; ms < 2; ms++) {
                        mma_f16(acc[ms][2 * g],     ah[ms], t0, t2);
                        mma_f16(acc[ms][2 * g + 1], ah[ms], t1, t3);
                    }
                    if (TWOPASS) {
                        uint32_t u0, u1, u2, u3;
                        ldm_x4(u0, u1, u2, u3, Bl + off);
#pragma unroll
                        for (int ms = 0; ms < 2; ms++) {
                            mma_f16(acc[ms][2 * g],     ah[ms], u0, u2);
                            mma_f16(acc[ms][2 * g + 1], ah[ms], u1, u3);
                        }
                    }
                }
            }
            __syncthreads();

            if (t == 8 && q + 1 < CINQ) {
                stageA(q + 1);
                stageB(q + 1, (s + 1) & 1);    // (t=0, q+1) -> kc = q+1
                cpa_commit();
            }
        }
    }

    // ---- stage [n][m=256] fp32 in smem (pitch 260) ----
    float* sepi = (float*)smc;
    const int em = mw * 32 + (lane >> 2);
    const int ecol = (lane & 3) * 2;
#pragma unroll
    for (int ms = 0; ms < 2; ms++) {
        int m = em + ms * 16;
#pragma unroll
        for (int g = 0; g < NG; g++) {
            int nb = nw * NW + g * 16 + ecol;
            sepi[nb * 260 + m]           = acc[ms][2 * g][0];
            sepi[(nb + 1) * 260 + m]     = acc[ms][2 * g][1];
            sepi[nb * 260 + m + 8]       = acc[ms][2 * g][2];
            sepi[(nb + 1) * 260 + m + 8] = acc[ms][2 * g][3];
            int nb2 = nb + 8;
            sepi[nb2 * 260 + m]           = acc[ms][2 * g + 1][0];
            sepi[(nb2 + 1) * 260 + m]     = acc[ms][2 * g + 1][1];
            sepi[nb2 * 260 + m + 8]       = acc[ms][2 * g + 1][2];
            sepi[(nb2 + 1) * 260 + m + 8] = acc[ms][2 * g + 1][3];
        }
    }
    __syncthreads();

    if (EPI == 0) {
        float* out = (float*)outv;
#pragma unroll
        for (int j = 0; j < NT / 8; j++) {
            int lin = j * 512 + tid;
            int n = lin >> 6;
            int seg = lin & 63;
            float4 v = *(float4*)(sepi + n * 260 + seg * 4);
            float bz = bias ? bias[oc0 + n] : 0.f;
            v.x += bz; v.y += bz; v.z += bz; v.w += bz;
            *(float4*)(out + (((size_t)(b * NTOT + oc0 + n)) << 16) + sb + seg * 4) = v;
        }
    } else if (EPI == 1) {
        float* out = (float*)outv;
#pragma unroll
        for (int j = 0; j < 8; j++) {
            int lin = j * 512 + tid;
            int m = lin >> 4;
            int cq = lin & 15;
            float4 v;
            v.x = sepi[(cq * 4 + 0) * 260 + m] + bias[cq * 4 + 0];
            v.y = sepi[(cq * 4 + 1) * 260 + m] + bias[cq * 4 + 1];
            v.z = sepi[(cq * 4 + 2) * 260 + m] + bias[cq * 4 + 2];
            v.w = sepi[(cq * 4 + 3) * 260 + m] + bias[cq * 4 + 3];
            *(float4*)(out + ((size_t)(b * 65536 + sb + m)) * 64 + cq * 4) = v;
        }
    } else {
        __half* out = (__half*)outv;
#pragma unroll
        for (int j = 0; j < NT / 8; j++) {
            int lin = j * 512 + tid;
            int n = lin >> 6;
            int seg = lin & 63;
            const float* sp = sepi + n * 260 + seg * 4;
            __half h0 = __float2half_rn(sp[0]);
            __half h1 = __float2half_rn(sp[1]);
            __half h2 = __float2half_rn(sp[2]);
            __half h3 = __float2half_rn(sp[3]);
            unsigned short hs[4] = {*(unsigned short*)&h0, *(unsigned short*)&h1,
                                    *(unsigned short*)&h2, *(unsigned short*)&h3};
            *(uint2*)((unsigned short*)out + (((size_t)(b * NTOT + oc0 + n)) << 16)
                      + sb + seg * 4) = *(uint2*)hs;
        }
    }

    if ((EPI == 0 || EPI == 1) && red) {
        float* sred = sepi + NT * 260;
        int n = tid >> 3, part = tid & 7;
        float bz = bias ? bias[oc0 + n] : 0.f;
        float s1 = 0.f, s2 = 0.f;
        const float* rowp = sepi + n * 260 + part * 32;
#pragma unroll
        for (int j = 0; j < 32; j++) {
            float v = rowp[j] + bz;
            s1 += v;
            s2 = fmaf(v, v, s2);
        }
        sred[(0 * 64 + n) * 8 + part] = s1;
        sred[(1 * 64 + n) * 8 + part] = s2;
        __syncthreads();
        if (tid < 128) {
            int which = tid >> 6, n2 = tid & 63;
            const float* pr = sred + (which * 64 + n2) * 8;
            float s = 0.f;
#pragma unroll
            for (int j = 0; j < 8; j++) s += pr[j];
            atomicAdd(red + which * 64 + oc0 + n2, s);
        }
    }
}

// ================= deformable gather (fp16 offsets) -> xd NHWC fp16 =================
__global__ void __launch_bounds__(256)
gathercvt_k(const float* __restrict__ x2, const float* __restrict__ up,
            const __half* __restrict__ offs, __half* __restrict__ oc)
{
    __shared__ float s[128][33];
    const int s0 = blockIdx.x * 32;
    const int b = blockIdx.y;
    const int tid = threadIdx.x;
    const int px = tid & 31;
    const int hw = s0 + px;
    const int h = hw >> 8;
    const int w = hw & 255;
#pragma unroll 4
    for (int c = tid >> 5; c < 128; c += 8) {
        const float* src = (c < 64) ? x2 + (b * 64 + c) * HWSZ
                                    : up + (b * 64 + (c - 64)) * HWSZ;
        int obase = b * C256 * HWSZ + c * 2 * HWSZ + h * (2 * WW) + 2 * w;
        float oy = __half2float(offs[obase]);
        float ox = __half2float(offs[obase + 1]);
        float cy = fminf(fmaxf(oy + (float)h, 0.f), 255.f);
        float cx = fminf(fmaxf(ox + (float)w, 0.f), 255.f);
        float y0f = floorf(cy), x0f = floorf(cx);
        int y0 = (int)y0f;
        int x0 = (int)x0f;
        int y1 = (int)ceilf(cy);
        int x1 = (int)ceilf(cx);
        float v00 = src[y0 * WW + x0];
        float v10 = src[y1 * WW + x0];
        float v01 = src[y0 * WW + x1];
        float v11 = src[y1 * WW + x1];
        float wy = cy - y0f, wx = cx - x0f;
        float vt = v00 + (v10 - v00) * wy;
        float vb = v01 + (v11 - v01) * wy;
        s[c][px] = vt + (vb - vt) * wx;
    }
    __syncthreads();
#pragma unroll 4
    for (int e = tid; e < 32 * 128; e += 256) {
        int p = e >> 7, c = e & 127;
        size_t idx = ((size_t)(b * HWSZ + s0 + p)) * 128 + c;
        oc[idx] = __float2half_rn(s[c][p]);
    }
}

// ================= small kernels =================
__global__ void zero_red_k() { g_red[threadIdx.x] = 0.f; }

__global__ void bnfin_k(const float* __restrict__ red,
                        const float* __restrict__ gamma, const float* __restrict__ beta,
                        float* __restrict__ ab)
{
    int c = threadIdx.x;
    const float invn = 1.f / 131072.f;
    float m = red[c] * invn;
    float var = fmaf(-m, m, red[64 + c] * invn);
    float a = gamma[c] * rsqrtf(var + 1e-5f);
    ab[c] = a;
    ab[64 + c] = fmaf(-m, a, beta[c]);
}

__global__ void __launch_bounds__(256)
afsplit_k(const float* __restrict__ in, const float* __restrict__ ab,
          __half* __restrict__ oc)
{
    int i4 = blockIdx.x * 256 + threadIdx.x;
    int c0 = (i4 & 15) * 4;
    float4 v = *(const float4*)(in + (size_t)i4 * 4);
    float vv[4] = {v.x, v.y, v.z, v.w};
    unsigned short hs[4];
#pragma unroll
    for (int j = 0; j < 4; j++) {
        int c = c0 + j;
        float y = fmaxf(fmaf(vv[j], __ldg(ab + c), __ldg(ab + 64 + c)), 0.f);
        __half hb = __float2half_rn(y);
        hs[j] = *(unsigned short*)&hb;
    }
    *(uint2*)((unsigned short*)oc + (size_t)i4 * 4) = *(uint2*)hs;
}

__global__ void __launch_bounds__(256)
bnrelu_out_k(const float* __restrict__ buf, const float* __restrict__ ab,
             float* __restrict__ out)
{
    int i4 = blockIdx.x * 256 + threadIdx.x;
    int c = (i4 >> 14) & 63;
    float a = __ldg(ab + c), bz = __ldg(ab + 64 + c);
    float4 v = *(const float4*)(buf + (size_t)i4 * 4);
    v.x = fmaxf(fmaf(v.x, a, bz), 0.f);
    v.y = fmaxf(fmaf(v.y, a, bz), 0.f);
    v.z = fmaxf(fmaf(v.z, a, bz), 0.f);
    v.w = fmaxf(fmaf(v.w, a, bz), 0.f);
    *(float4*)(out + (size_t)i4 * 4) = v;
}

// ================= launch =================
extern "C" void kernel_launch(void* const* d_in, const int* in_sizes, int n_in,
                              void* d_out, int out_size)
{
    const float* x1   = (const float*)d_in[0];
    const float* x2   = (const float*)d_in[1];
    const float* up_w = (const float*)d_in[2];
    const float* up_b = (const float*)d_in[3];
    const float* offw = (const float*)d_in[4];
    const float* c1w  = (const float*)d_in[5];
    const float* c1b  = (const float*)d_in[6];
    const float* g1   = (const float*)d_in[7];
    const float* b1   = (const float*)d_in[8];
    const float* c2w  = (const float*)d_in[9];
    const float* c2b  = (const float*)d_in[10];
    const float* g2   = (const float*)d_in[11];
    const float* b2   = (const float*)d_in[12];
    float* outp = (float*)d_out;

    float *p_up, *p_h1raw, *p_b2, *p_red, *p_ab1, *p_ab2;
    cudaGetSymbolAddress((void**)&p_up,    g_up);
    cudaGetSymbolAddress((void**)&p_h1raw, g_h1raw);
    cudaGetSymbolAddress((void**)&p_b2,    g_b2);
    cudaGetSymbolAddress((void**)&p_red,   g_red);
    cudaGetSymbolAddress((void**)&p_ab1,   g_ab1);
    cudaGetSymbolAddress((void**)&p_ab2,   g_ab2);
    __nv_bfloat16 *p_x1_h, *p_x1_l, *p_wu_h, *p_wu_l;
    cudaGetSymbolAddress((void**)&p_x1_h, g_x1_h);
    cudaGetSymbolAddress((void**)&p_x1_l, g_x1_l);
    cudaGetSymbolAddress((void**)&p_wu_h, g_wu_h);
    cudaGetSymbolAddress((void**)&p_wu_l, g_wu_l);
    __half *p_off, *p_cat, *p_xd, *p_h1, *p_wo, *p_w1h, *p_w1l, *p_w2h, *p_w2l;
    cudaGetSymbolAddress((void**)&p_off, g_off);
    cudaGetSymbolAddress((void**)&p_cat, g_cat);
    cudaGetSymbolAddress((void**)&p_xd,  g_xd);
    cudaGetSymbolAddress((void**)&p_h1,  g_h1);
    cudaGetSymbolAddress((void**)&p_wo,  g_wo);
    cudaGetSymbolAddress((void**)&p_w1h, g_w1h);
    cudaGetSymbolAddress((void**)&p_w1l, g_w1l);
    cudaGetSymbolAddress((void**)&p_w2h, g_w2h);
    cudaGetSymbolAddress((void**)&p_w2l, g_w2l);

    const int smem_rs = 135168;            // covers all convrs variants
    const int smem_up = 49152 + 1024;
    cudaFuncSetAttribute(convrs_k<256, 2, 128, 2, 0>, cudaFuncAttributeMaxDynamicSharedMemorySize, smem_rs);
    cudaFuncSetAttribute(convrs_k<64, 2, 64, 1, 1>,   cudaFuncAttributeMaxDynamicSharedMemorySize, smem_rs);
    cudaFuncSetAttribute(convrs_k<64, 1, 64, 0, 1>,   cudaFuncAttributeMaxDynamicSharedMemorySize, smem_rs);
    cudaFuncSetAttribute(upmma_k, cudaFuncAttributeMaxDynamicSharedMemorySize, smem_up);

    // 0) zero stats + weight prep
    zero_red_k<<<1, 256>>>();
    wprep_f16_k<<<(256 * 128 * 9 + 255) / 256, 256>>>(offw, p_wo, 256, 128);
    wprep_f16x2_k<<<(64 * 128 * 9 + 255) / 256, 256>>>(c1w, p_w1h, p_w1l, 64, 128);
    wprep_f16x2_k<<<(64 * 64 * 9 + 255) / 256, 256>>>(c2w, p_w2h, p_w2l, 64, 64);
    upwprep_k<<<64, 256>>>(up_w, p_wu_h, p_wu_l);

    // 1) x1 -> NHWC bf16 hi/lo, upconv via bf16x3 mma
    tc_x1_k<<<dim3(512, 2), 256>>>(x1, p_x1_h, p_x1_l);
    upmma_k<<<dim3(256, 4), 256, smem_up>>>(p_x1_h, p_x1_l, p_wu_h, p_wu_l, up_b, p_up);

    // 2) concat -> NHWC fp16
    tc_cat_k<<<dim3(2048, 2), 256>>>(x2, p_up, p_cat);

    // 3) row-staged offset conv -> g_off fp16 NCHW
    convrs_k<256, 2, 128, 2, 0><<<dim3(512, 2), 512, smem_rs>>>(
        p_cat, p_wo, nullptr, nullptr, p_off, nullptr);

    // 4) gather (fp16 offsets) -> xd NHWC fp16
    gathercvt_k<<<dim3(2048, 2), 256>>>(x2, p_up, p_off, p_xd);

    // 5) row-staged conv1 (fp16 2-pass) -> NHWC fp32 + BN1 stats
    convrs_k<64, 2, 64, 1, 1><<<dim3(512, 1), 512, smem_rs>>>(
        p_xd, p_w1h, p_w1l, c1b, p_h1raw, p_red);
    bnfin_k<<<1, 64>>>(p_red, g1, b1, p_ab1);

    // 6) BN1 affine + relu -> fp16
    afsplit_k<<<8192, 256>>>(p_h1raw, p_ab1, p_h1);

    // 7) row-staged conv2 (fp16 2-pass) -> NCHW fp32 + BN2 stats
    convrs_k<64, 1, 64, 0, 1><<<dim3(512, 1), 512, smem_rs>>>(
        p_h1, p_w2h, p_w2l, c2b, p_b2, p_red + 128);
    bnfin_k<<<1, 64>>>(p_red + 128, g2, b2, p_ab2);

    // 8) final BN+ReLU
    bnrelu_out_k<<<8192, 256>>>(p_b2, p_ab2, outp);
}

// round 11
// speedup vs baseline: 2.2377x; 1.1115x over previous
#include <cuda_runtime.h>
#include <cuda_bf16.h>
#include <cuda_fp16.h>
#include <math.h>
#include <stdint.h>

#define HH 256
#define WW 256
#define HWSZ 65536
#define BB 2
#define C64 64
#define C128 128
#define C256 256

#define SW128(off) ((off) ^ (((off) >> 3) & 0x70))

__device__ __forceinline__ uint32_t smem_u32(const void* p) {
    uint32_t a;
    asm("{ .reg .u64 t; cvta.to.shared.u64 t, %1; cvt.u32.u64 %0, t; }" : "=r"(a) : "l"(p));
    return a;
}
__device__ __forceinline__ void cpa16(uint32_t dst, const void* src, int sz) {
    asm volatile("cp.async.cg.shared.global [%0], [%1], 16, %2;"
                 :: "r"(dst), "l"(src), "r"(sz) : "memory");
}
__device__ __forceinline__ void cpa_commit() {
    asm volatile("cp.async.commit_group;" ::: "memory");
}
template<int N>
__device__ __forceinline__ void cpa_wait() {
    asm volatile("cp.async.wait_group %0;" :: "n"(N) : "memory");
}
__device__ __forceinline__ void ldm_x4(uint32_t& r0, uint32_t& r1, uint32_t& r2, uint32_t& r3,
                                       uint32_t addr) {
    asm volatile("ldmatrix.sync.aligned.m8n8.x4.shared.b16 {%0,%1,%2,%3}, [%4];"
                 : "=r"(r0), "=r"(r1), "=r"(r2), "=r"(r3) : "r"(addr));
}
__device__ __forceinline__ void mma_bf16(float* c, const uint32_t* a, uint32_t b0, uint32_t b1) {
    asm volatile("mma.sync.aligned.m16n8k16.row.col.f32.bf16.bf16.f32 "
                 "{%0,%1,%2,%3}, {%4,%5,%6,%7}, {%8,%9}, {%0,%1,%2,%3};"
                 : "+f"(c[0]), "+f"(c[1]), "+f"(c[2]), "+f"(c[3])
                 : "r"(a[0]), "r"(a[1]), "r"(a[2]), "r"(a[3]), "r"(b0), "r"(b1));
}
__device__ __forceinline__ void mma_f16(float* c, const uint32_t* a, uint32_t b0, uint32_t b1) {
    asm volatile("mma.sync.aligned.m16n8k16.row.col.f32.f16.f16.f32 "
                 "{%0,%1,%2,%3}, {%4,%5,%6,%7}, {%8,%9}, {%0,%1,%2,%3};"
                 : "+f"(c[0]), "+f"(c[1]), "+f"(c[2]), "+f"(c[3])
                 : "r"(a[0]), "r"(a[1]), "r"(a[2]), "r"(a[3]), "r"(b0), "r"(b1));
}

// ================= scratch (device globals) =================
__device__ float g_up   [BB * C64 * HWSZ];
__device__ __half g_off [BB * C256 * HWSZ];
__device__ float g_h1raw[BB * HWSZ * C64];
__device__ float g_b2   [BB * C64 * HWSZ];
__device__ float g_red[256];
__device__ float g_ab1[128];
__device__ float g_ab2[128];
__device__ __nv_bfloat16 g_x1_h[BB * 16384 * C64];
__device__ __nv_bfloat16 g_x1_l[BB * 16384 * C64];
__device__ __nv_bfloat16 g_wu_h[C256 * 64];
__device__ __nv_bfloat16 g_wu_l[C256 * 64];
__device__ __half g_cat [BB * HWSZ * C128];
__device__ __half g_xd  [BB * HWSZ * C128];
__device__ __half g_wo  [18 * C256 * 64];
__device__ __half g_w1  [18 * C64 * 64];
__device__ __half g_w2  [9 * C64 * 64];

// ================= weight prep =================
__global__ void wprep_f16_k(const float* __restrict__ w, __half* __restrict__ wh,
                            int N, int CIN)
{
    int i = blockIdx.x * blockDim.x + threadIdx.x;
    if (i >= N * CIN * 9) return;
    int t  = i % 9;
    int ci = (i / 9) % CIN;
    int o  = i / (9 * CIN);
    int q = ci >> 6, cc = ci & 63;
    int kc = t * (CIN >> 6) + q;
    wh[(kc * N + o) * 64 + cc] = __float2half_rn(w[i]);
}
__global__ void upwprep_k(const float* __restrict__ w, __nv_bfloat16* __restrict__ wh,
                          __nv_bfloat16* __restrict__ wl)
{
    int s = blockIdx.x * blockDim.x + threadIdx.x;
    if (s >= 64 * 256) return;
    int n = s & 255;
    int cc = s >> 8;
    float v = w[s];
    __nv_bfloat16 h = __float2bfloat16(v);
    float lo = v - __bfloat162float(h);
    wh[n * 64 + cc] = h;
    wl[n * 64 + cc] = __float2bfloat16(lo);
}

// ================= x1 NCHW -> NHWC bf16 hi/lo =================
__global__ void __launch_bounds__(256)
tc_x1_k(const float* __restrict__ in0,
        __nv_bfloat16* __restrict__ oh, __nv_bfloat16* __restrict__ ol)
{
    __shared__ float s[64][33];
    const int s0 = blockIdx.x * 32;
    const int b = blockIdx.y;
    const int tid = threadIdx.x;
    const int px = tid & 31;
#pragma unroll 4
    for (int c = tid >> 5; c < 64; c += 8)
        s[c][px] = in0[(b * 64 + c) * 16384 + s0 + px];
    __syncthreads();
#pragma unroll 4
    for (int e = tid; e < 32 * 64; e += 256) {
        int p = e >> 6, c = e & 63;
        float v = s[c][p];
        __nv_bfloat16 h = __float2bfloat16(v);
        float lo = v - __bfloat162float(h);
        size_t idx = ((size_t)(b * 16384 + s0 + p)) * 64 + c;
        oh[idx] = h;
        ol[idx] = __float2bfloat16(lo);
    }
}

// ================= concat -> NHWC fp16 =================
__global__ void __launch_bounds__(256)
tc_cat_k(const float* __restrict__ x2, const float* __restrict__ up,
         __half* __restrict__ oc)
{
    __shared__ float s[128][33];
    const int s0 = blockIdx.x * 32;
    const int b = blockIdx.y;
    const int tid = threadIdx.x;
    const int px = tid & 31;
#pragma unroll 4
    for (int c = tid >> 5; c < 128; c += 8) {
        const float* src = (c < 64) ? x2 + (b * 64 + c) * HWSZ
                                    : up + (b * 64 + (c - 64)) * HWSZ;
        s[c][px] = src[s0 + px];
    }
    __syncthreads();
#pragma unroll 4
    for (int e = tid; e < 32 * 128; e += 256) {
        int p = e >> 7, c = e & 127;
        size_t idx = ((size_t)(b * HWSZ + s0 + p)) * 128 + c;
        oc[idx] = __float2half_rn(s[c][p]);
    }
}

// ================= upconv via mma (bf16x3) =================
__global__ void __launch_bounds__(256, 2)
upmma_k(const __nv_bfloat16* __restrict__ ah_g, const __nv_bfloat16* __restrict__ al_g,
        const __nv_bfloat16* __restrict__ bh_g, const __nv_bfloat16* __restrict__ bl_g,
        const float* __restrict__ upb, float* __restrict__ up)
{
    extern __shared__ char dsm[];
    constexpr int A_H = 0, A_L = 16384, B_H = 32768, B_L = 40960;
    uint32_t raw = smem_u32(dsm);
    uint32_t base = (raw + 1023u) & ~1023u;
    char* smc = dsm + (base - raw);
    const int tid = threadIdx.x;
    const int wid = tid >> 5;
    const int lane = tid & 31;

    const int p0 = blockIdx.x * 128;
    const int b  = p0 >> 14;
    const int sb = p0 & 16383;
    const int y0 = sb >> 7;
    const int oc0 = blockIdx.y * 64;

#pragma unroll
    for (int it = 0; it < 4; it++) {
        int idx = it * 256 + tid;
        int m = idx >> 3, ch = idx & 7;
        size_t gi = ((size_t)(p0 + m)) * 64 + ch * 8;
        uint32_t sw = SW128(m * 128 + ch * 16);
        cpa16(base + A_H + sw, ah_g + gi, 16);
        cpa16(base + A_L + sw, al_g + gi, 16);
    }
#pragma unroll
    for (int it = 0; it < 2; it++) {
        int idx = it * 256 + tid;
        int o = idx >> 3, ch = idx & 7;
        size_t gi = ((size_t)(oc0 + o)) * 64 + ch * 8;
        uint32_t sw = SW128(o * 128 + ch * 16);
        cpa16(base + B_H + sw, bh_g + gi, 16);
        cpa16(base + B_L + sw, bl_g + gi, 16);
    }
    cpa_commit();
    cpa_wait<0>();
    __syncthreads();

    float acc[8][4];
#pragma unroll
    for (int g = 0; g < 8; g++)
#pragma unroll
        for (int j = 0; j < 4; j++) acc[g][j] = 0.f;

    const uint32_t Ah = base + A_H, Al = base + A_L;
    const uint32_t Bh = base + B_H, Bl = base + B_L;
    const int arow = wid * 16 + (lane & 15);
    const int nrow = lane & 15;
    const int chalf = (lane >> 4) * 16;
#pragma unroll
    for (int kk = 0; kk < 4; kk++) {
        const int cb = chalf + kk * 32;
        uint32_t ah[4], al[4];
        ldm_x4(ah[0], ah[1], ah[2], ah[3], Ah + SW128(arow * 128 + cb));
        ldm_x4(al[0], al[1], al[2], al[3], Al + SW128(arow * 128 + cb));
#pragma unroll
        for (int g = 0; g < 4; g++) {
            uint32_t off = SW128((g * 16 + nrow) * 128 + cb);
            uint32_t t0, t1, t2, t3, u0, u1, u2, u3;
            ldm_x4(t0, t1, t2, t3, Bh + off);
            ldm_x4(u0, u1, u2, u3, Bl + off);
            mma_bf16(acc[2 * g],     ah, t0, t2);
            mma_bf16(acc[2 * g + 1], ah, t1, t3);
            mma_bf16(acc[2 * g],     al, t0, t2);
            mma_bf16(acc[2 * g + 1], al, t1, t3);
            mma_bf16(acc[2 * g],     ah, u0, u2);
            mma_bf16(acc[2 * g + 1], ah, u1, u3);
        }
    }
    __syncthreads();

    float* sepi = (float*)smc;
    const int em = wid * 16 + (lane >> 2);
    const int en = (lane & 3) * 2;
#pragma unroll
    for (int g = 0; g < 8; g++) {
        int n0 = g * 8 + en;
        sepi[n0 * 132 + em]           = acc[g][0];
        sepi[(n0 + 1) * 132 + em]     = acc[g][1];
        sepi[n0 * 132 + em + 8]       = acc[g][2];
        sepi[(n0 + 1) * 132 + em + 8] = acc[g][3];
    }
    __syncthreads();
#pragma unroll 4
    for (int j = 0; j < 32; j++) {
        int lin = j * 256 + tid;
        int n = lin >> 7, m = lin & 127;
        int ng = oc0 + n;
        int o = ng >> 2, k = (ng >> 1) & 1, l = ng & 1;
        float v = sepi[n * 132 + m] + upb[o];
        up[((size_t)(b * 64 + o) << 16) + (2 * y0 + k) * 256 + 2 * m + l] = v;
    }
}

// ============ ROW-STAGED implicit-GEMM 3x3 conv (generalized) ============
// A band (3 x 258 px of 64ch) staged once per 64-ch group; 9 taps by row shift.
// B double-buffered per tap. Weight index kc = t*CINQ + q.
// AFF=1 (requires CINQ==1): A is fp32 NHWC with per-channel affine+relu applied
// during staging (fuses BN1+ReLU; plain loads + STS instead of cp.async).
// EPI 0: NCHW fp32 + bias + stats. EPI 1: NHWC fp32 + bias + stats.
// EPI 2: NCHW fp16 (no bias/stats).
template<int NTOT, int CINQ, int NT, int EPI, int AFF>
__global__ void __launch_bounds__(512)
convrs_k(const void* __restrict__ a_gv,
         const __half* __restrict__ bh_g,
         const float* __restrict__ aff,
         const float* __restrict__ bias, void* __restrict__ outv,
         float* __restrict__ red)
{
    extern __shared__ char dsm[];
    constexpr int CCH = CINQ * 64;
    constexpr int NW  = NT / 2;
    constexpr int NG  = NW / 16;
    constexpr int A_BYTES = 776 * 128;
    constexpr int B_OFF = A_BYTES;              // 99328
    constexpr int B_BUF = NT * 128;

    uint32_t raw = smem_u32(dsm);
    uint32_t base = (raw + 1023u) & ~1023u;
    char* smc = dsm + (base - raw);
    const int tid = threadIdx.x;
    const int wid = tid >> 5;
    const int lane = tid & 31;
    const int mw = wid & 7;
    const int nw = wid >> 3;

    const int b  = blockIdx.x >> 8;
    const int y0 = blockIdx.x & 255;
    const int sb = y0 << 8;
    const int oc0 = blockIdx.y * NT;

    auto stageA = [&](int q) {
        if (AFF) {
            const float* a32 = (const float*)a_gv;
            for (int idx = tid; idx < 6192; idx += 512) {
                int p = idx >> 3, ch = idx & 7;
                int brow = p / 258;
                int bcol = p - brow * 258;
                int gy = y0 + brow - 1;
                int gx = bcol - 1;
                bool inb = ((unsigned)gy < 256u) && ((unsigned)gx < 256u);
                uint4 pk = make_uint4(0, 0, 0, 0);
                if (inb) {
                    size_t gi = (((size_t)b << 16) + (gy << 8) + gx) * 64 + ch * 8;
                    float4 v0 = *(const float4*)(a32 + gi);
                    float4 v1 = *(const float4*)(a32 + gi + 4);
                    float vv[8] = {v0.x, v0.y, v0.z, v0.w, v1.x, v1.y, v1.z, v1.w};
                    unsigned short hs[8];
#pragma unroll
                    for (int j = 0; j < 8; j++) {
                        int c = ch * 8 + j;
                        float y = fmaxf(fmaf(vv[j], __ldg(aff + c), __ldg(aff + 64 + c)), 0.f);
                        __half hb = __float2half_rn(y);
                        hs[j] = *(unsigned short*)&hb;
                    }
                    pk = *(uint4*)hs;
                }
                *(uint4*)(smc + SW128(p * 128 + ch * 16)) = pk;
            }
        } else {
            const __half* a_g = (const __half*)a_gv;
            for (int idx = tid; idx < 6192; idx += 512) {
                int p = idx >> 3, ch = idx & 7;
                int brow = p / 258;
                int bcol = p - brow * 258;
                int gy = y0 + brow - 1;
                int gx = bcol - 1;
                bool inb = ((unsigned)gy < 256u) && ((unsigned)gx < 256u);
                size_t gi = (((size_t)b << 16) + (gy << 8) + gx) * CCH + q * 64 + ch * 8;
                if (!inb) gi = 0;
                cpa16(base + SW128(p * 128 + ch * 16), a_g + gi, inb ? 16 : 0);
            }
        }
    };
    auto stageB = [&](int kc, int buf) {
        const uint32_t bbase = base + B_OFF + buf * B_BUF;
        for (int idx = tid; idx < NT * 8; idx += 512) {
            int o = idx >> 3, ch = idx & 7;
            size_t gi = ((size_t)kc * NTOT + oc0 + o) * 64 + ch * 8;
            cpa16(bbase + SW128(o * 128 + ch * 16), bh_g + gi, 16);
        }
    };

    float acc[2][NW / 8][4];
#pragma unroll
    for (int ms = 0; ms < 2; ms++)
#pragma unroll
        for (int g = 0; g < NW / 8; g++)
#pragma unroll
            for (int j = 0; j < 4; j++) acc[ms][g][j] = 0.f;

    stageA(0);
    stageB(0, 0);
    cpa_commit();

    const int chalf = (lane >> 4) * 16;
    const int nrow = lane & 15;
    const int arowb = mw * 32 + (lane & 15);

#pragma unroll 1
    for (int q = 0; q < CINQ; q++) {
#pragma unroll 1
        for (int t = 0; t < 9; t++) {
            const int s = q * 9 + t;
            if (t < 8) {
                stageB((t + 1) * CINQ + q, (s + 1) & 1);
                cpa_commit();
                cpa_wait<1>();
            } else {
                cpa_wait<0>();
            }
            __syncthreads();

            const int ky = t / 3 - 1;
            const int kx = t % 3 - 1;
            const uint32_t Bb = base + B_OFF + (s & 1) * B_BUF;
            const int rb = (ky + 1) * 258 + kx + 1 + arowb;

#pragma unroll
            for (int kk = 0; kk < 4; kk++) {
                const int cb = chalf + kk * 32;
                uint32_t ah[2][4];
#pragma unroll
                for (int ms = 0; ms < 2; ms++) {
                    int r = rb + ms * 16;
                    ldm_x4(ah[ms][0], ah[ms][1], ah[ms][2], ah[ms][3],
                           base + SW128(r * 128 + cb));
                }
#pragma unroll
                for (int g = 0; g < NG; g++) {
                    uint32_t off = SW128((nw * NW + g * 16 + nrow) * 128 + cb);
                    uint32_t t0, t1, t2, t3;
                    ldm_x4(t0, t1, t2, t3, Bb + off);
#pragma unroll
                    for (int ms = 0; ms < 2; ms++) {
                        mma_f16(acc[ms][2 * g],     ah[ms], t0, t2);
                        mma_f16(acc[ms][2 * g + 1], ah[ms], t1, t3);
                    }
                }
            }
            __syncthreads();

            if (t == 8 && q + 1 < CINQ) {
                stageA(q + 1);
                stageB(q + 1, (s + 1) & 1);
                cpa_commit();
            }
        }
    }

    // ---- stage [n][m=256] fp32 in smem (pitch 260) ----
    float* sepi = (float*)smc;
    const int em = mw * 32 + (lane >> 2);
    const int ecol = (lane & 3) * 2;
#pragma unroll
    for (int ms = 0; ms < 2; ms++) {
        int m = em + ms * 16;
#pragma unroll
        for (int g = 0; g < NG; g++) {
            int nb = nw * NW + g * 16 + ecol;
            sepi[nb * 260 + m]           = acc[ms][2 * g][0];
            sepi[(nb + 1) * 260 + m]     = acc[ms][2 * g][1];
            sepi[nb * 260 + m + 8]       = acc[ms][2 * g][2];
            sepi[(nb + 1) * 260 + m + 8] = acc[ms][2 * g][3];
            int nb2 = nb + 8;
            sepi[nb2 * 260 + m]           = acc[ms][2 * g + 1][0];
            sepi[(nb2 + 1) * 260 + m]     = acc[ms][2 * g + 1][1];
            sepi[nb2 * 260 + m + 8]       = acc[ms][2 * g + 1][2];
            sepi[(nb2 + 1) * 260 + m + 8] = acc[ms][2 * g + 1][3];
        }
    }
    __syncthreads();

    if (EPI == 0) {
        float* out = (float*)outv;
#pragma unroll
        for (int j = 0; j < NT / 8; j++) {
            int lin = j * 512 + tid;
            int n = lin >> 6;
            int seg = lin & 63;
            float4 v = *(float4*)(sepi + n * 260 + seg * 4);
            float bz = bias ? bias[oc0 + n] : 0.f;
            v.x += bz; v.y += bz; v.z += bz; v.w += bz;
            *(float4*)(out + (((size_t)(b * NTOT + oc0 + n)) << 16) + sb + seg * 4) = v;
        }
    } else if (EPI == 1) {
        float* out = (float*)outv;
#pragma unroll
        for (int j = 0; j < 8; j++) {
            int lin = j * 512 + tid;
            int m = lin >> 4;
            int cq = lin & 15;
            float4 v;
            v.x = sepi[(cq * 4 + 0) * 260 + m] + bias[cq * 4 + 0];
            v.y = sepi[(cq * 4 + 1) * 260 + m] + bias[cq * 4 + 1];
            v.z = sepi[(cq * 4 + 2) * 260 + m] + bias[cq * 4 + 2];
            v.w = sepi[(cq * 4 + 3) * 260 + m] + bias[cq * 4 + 3];
            *(float4*)(out + ((size_t)(b * 65536 + sb + m)) * 64 + cq * 4) = v;
        }
    } else {
        __half* out = (__half*)outv;
#pragma unroll
        for (int j = 0; j < NT / 8; j++) {
            int lin = j * 512 + tid;
            int n = lin >> 6;
            int seg = lin & 63;
            const float* sp = sepi + n * 260 + seg * 4;
            __half h0 = __float2half_rn(sp[0]);
            __half h1 = __float2half_rn(sp[1]);
            __half h2 = __float2half_rn(sp[2]);
            __half h3 = __float2half_rn(sp[3]);
            unsigned short hs[4] = {*(unsigned short*)&h0, *(unsigned short*)&h1,
                                    *(unsigned short*)&h2, *(unsigned short*)&h3};
            *(uint2*)((unsigned short*)out + (((size_t)(b * NTOT + oc0 + n)) << 16)
                      + sb + seg * 4) = *(uint2*)hs;
        }
    }

    if ((EPI == 0 || EPI == 1) && red) {
        float* sred = sepi + NT * 260;
        int n = tid >> 3, part = tid & 7;
        float bz = bias ? bias[oc0 + n] : 0.f;
        float s1 = 0.f, s2 = 0.f;
        const float* rowp = sepi + n * 260 + part * 32;
#pragma unroll
        for (int j = 0; j < 32; j++) {
            float v = rowp[j] + bz;
            s1 += v;
            s2 = fmaf(v, v, s2);
        }
        sred[(0 * 64 + n) * 8 + part] = s1;
        sred[(1 * 64 + n) * 8 + part] = s2;
        __syncthreads();
        if (tid < 128) {
            int which = tid >> 6, n2 = tid & 63;
            const float* pr = sred + (which * 64 + n2) * 8;
            float s = 0.f;
#pragma unroll
            for (int j = 0; j < 8; j++) s += pr[j];
            atomicAdd(red + which * 64 + oc0 + n2, s);
        }
    }
}

// ================= deformable gather (fp16 offsets) -> xd NHWC fp16 =================
__global__ void __launch_bounds__(256)
gathercvt_k(const float* __restrict__ x2, const float* __restrict__ up,
            const __half* __restrict__ offs, __half* __restrict__ oc)
{
    __shared__ float s[128][33];
    const int s0 = blockIdx.x * 32;
    const int b = blockIdx.y;
    const int tid = threadIdx.x;
    const int px = tid & 31;
    const int hw = s0 + px;
    const int h = hw >> 8;
    const int w = hw & 255;
#pragma unroll 4
    for (int c = tid >> 5; c < 128; c += 8) {
        const float* src = (c < 64) ? x2 + (b * 64 + c) * HWSZ
                                    : up + (b * 64 + (c - 64)) * HWSZ;
        int obase = b * C256 * HWSZ + c * 2 * HWSZ + h * (2 * WW) + 2 * w;
        float oy = __half2float(offs[obase]);
        float ox = __half2float(offs[obase + 1]);
        float cy = fminf(fmaxf(oy + (float)h, 0.f), 255.f);
        float cx = fminf(fmaxf(ox + (float)w, 0.f), 255.f);
        float y0f = floorf(cy), x0f = floorf(cx);
        int y0 = (int)y0f;
        int x0 = (int)x0f;
        int y1 = (int)ceilf(cy);
        int x1 = (int)ceilf(cx);
        float v00 = src[y0 * WW + x0];
        float v10 = src[y1 * WW + x0];
        float v01 = src[y0 * WW + x1];
        float v11 = src[y1 * WW + x1];
        float wy = cy - y0f, wx = cx - x0f;
        float vt = v00 + (v10 - v00) * wy;
        float vb = v01 + (v11 - v01) * wy;
        s[c][px] = vt + (vb - vt) * wx;
    }
    __syncthreads();
#pragma unroll 4
    for (int e = tid; e < 32 * 128; e += 256) {
        int p = e >> 7, c = e & 127;
        size_t idx = ((size_t)(b * HWSZ + s0 + p)) * 128 + c;
        oc[idx] = __float2half_rn(s[c][p]);
    }
}

// ================= small kernels =================
__global__ void zero_red_k() { g_red[threadIdx.x] = 0.f; }

__global__ void bnfin_k(const float* __restrict__ red,
                        const float* __restrict__ gamma, const float* __restrict__ beta,
                        float* __restrict__ ab)
{
    int c = threadIdx.x;
    const float invn = 1.f / 131072.f;
    float m = red[c] * invn;
    float var = fmaf(-m, m, red[64 + c] * invn);
    float a = gamma[c] * rsqrtf(var + 1e-5f);
    ab[c] = a;
    ab[64 + c] = fmaf(-m, a, beta[c]);
}

__global__ void __launch_bounds__(256)
bnrelu_out_k(const float* __restrict__ buf, const float* __restrict__ ab,
             float* __restrict__ out)
{
    int i4 = blockIdx.x * 256 + threadIdx.x;
    int c = (i4 >> 14) & 63;
    float a = __ldg(ab + c), bz = __ldg(ab + 64 + c);
    float4 v = *(const float4*)(buf + (size_t)i4 * 4);
    v.x = fmaxf(fmaf(v.x, a, bz), 0.f);
    v.y = fmaxf(fmaf(v.y, a, bz), 0.f);
    v.z = fmaxf(fmaf(v.z, a, bz), 0.f);
    v.w = fmaxf(fmaf(v.w, a, bz), 0.f);
    *(float4*)(out + (size_t)i4 * 4) = v;
}

// ================= launch =================
extern "C" void kernel_launch(void* const* d_in, const int* in_sizes, int n_in,
                              void* d_out, int out_size)
{
    const float* x1   = (const float*)d_in[0];
    const float* x2   = (const float*)d_in[1];
    const float* up_w = (const float*)d_in[2];
    const float* up_b = (const float*)d_in[3];
    const float* offw = (const float*)d_in[4];
    const float* c1w  = (const float*)d_in[5];
    const float* c1b  = (const float*)d_in[6];
    const float* g1   = (const float*)d_in[7];
    const float* b1   = (const float*)d_in[8];
    const float* c2w  = (const float*)d_in[9];
    const float* c2b  = (const float*)d_in[10];
    const float* g2   = (const float*)d_in[11];
    const float* b2   = (const float*)d_in[12];
    float* outp = (float*)d_out;

    float *p_up, *p_h1raw, *p_b2, *p_red, *p_ab1, *p_ab2;
    cudaGetSymbolAddress((void**)&p_up,    g_up);
    cudaGetSymbolAddress((void**)&p_h1raw, g_h1raw);
    cudaGetSymbolAddress((void**)&p_b2,    g_b2);
    cudaGetSymbolAddress((void**)&p_red,   g_red);
    cudaGetSymbolAddress((void**)&p_ab1,   g_ab1);
    cudaGetSymbolAddress((void**)&p_ab2,   g_ab2);
    __nv_bfloat16 *p_x1_h, *p_x1_l, *p_wu_h, *p_wu_l;
    cudaGetSymbolAddress((void**)&p_x1_h, g_x1_h);
    cudaGetSymbolAddress((void**)&p_x1_l, g_x1_l);
    cudaGetSymbolAddress((void**)&p_wu_h, g_wu_h);
    cudaGetSymbolAddress((void**)&p_wu_l, g_wu_l);
    __half *p_off, *p_cat, *p_xd, *p_wo, *p_w1, *p_w2;
    cudaGetSymbolAddress((void**)&p_off, g_off);
    cudaGetSymbolAddress((void**)&p_cat, g_cat);
    cudaGetSymbolAddress((void**)&p_xd,  g_xd);
    cudaGetSymbolAddress((void**)&p_wo,  g_wo);
    cudaGetSymbolAddress((void**)&p_w1,  g_w1);
    cudaGetSymbolAddress((void**)&p_w2,  g_w2);

    const int smem_rs = 135168;
    const int smem_up = 49152 + 1024;
    cudaFuncSetAttribute(convrs_k<256, 2, 128, 2, 0>, cudaFuncAttributeMaxDynamicSharedMemorySize, smem_rs);
    cudaFuncSetAttribute(convrs_k<64, 2, 64, 1, 0>,   cudaFuncAttributeMaxDynamicSharedMemorySize, smem_rs);
    cudaFuncSetAttribute(convrs_k<64, 1, 64, 0, 1>,   cudaFuncAttributeMaxDynamicSharedMemorySize, smem_rs);
    cudaFuncSetAttribute(upmma_k, cudaFuncAttributeMaxDynamicSharedMemorySize, smem_up);

    // 0) zero stats + weight prep (all single-plane fp16)
    zero_red_k<<<1, 256>>>();
    wprep_f16_k<<<(256 * 128 * 9 + 255) / 256, 256>>>(offw, p_wo, 256, 128);
    wprep_f16_k<<<(64 * 128 * 9 + 255) / 256, 256>>>(c1w, p_w1, 64, 128);
    wprep_f16_k<<<(64 * 64 * 9 + 255) / 256, 256>>>(c2w, p_w2, 64, 64);
    upwprep_k<<<64, 256>>>(up_w, p_wu_h, p_wu_l);

    // 1) x1 -> NHWC bf16 hi/lo, upconv via bf16x3 mma
    tc_x1_k<<<dim3(512, 2), 256>>>(x1, p_x1_h, p_x1_l);
    upmma_k<<<dim3(256, 4), 256, smem_up>>>(p_x1_h, p_x1_l, p_wu_h, p_wu_l, up_b, p_up);

    // 2) concat -> NHWC fp16
    tc_cat_k<<<dim3(2048, 2), 256>>>(x2, p_up, p_cat);

    // 3) row-staged offset conv (1-pass) -> g_off fp16 NCHW
    convrs_k<256, 2, 128, 2, 0><<<dim3(512, 2), 512, smem_rs>>>(
        p_cat, p_wo, nullptr, nullptr, p_off, nullptr);

    // 4) gather (fp16 offsets) -> xd NHWC fp16
    gathercvt_k<<<dim3(2048, 2), 256>>>(x2, p_up, p_off, p_xd);

    // 5) row-staged conv1 (1-pass) -> NHWC fp32 + BN1 stats
    convrs_k<64, 2, 64, 1, 0><<<dim3(512, 1), 512, smem_rs>>>(
        p_xd, p_w1, nullptr, c1b, p_h1raw, p_red);
    bnfin_k<<<1, 64>>>(p_red, g1, b1, p_ab1);

    // 6) row-staged conv2 (1-pass, fused BN1 affine+relu on A-stage) -> NCHW fp32 + BN2 stats
    convrs_k<64, 1, 64, 0, 1><<<dim3(512, 1), 512, smem_rs>>>(
        p_h1raw, p_w2, p_ab1, c2b, p_b2, p_red + 128);
    bnfin_k<<<1, 64>>>(p_red + 128, g2, b2, p_ab2);

    // 7) final BN+ReLU
    bnrelu_out_k<<<8192, 256>>>(p_b2, p_ab2, outp);
}